// round 4
// baseline (speedup 1.0000x reference)
#include <cuda_runtime.h>

#define BSZ  2
#define DM   256
#define LSEQ 4096
#define DI   256
#define DS   16

// ---------------- scratch (static device globals; no runtime alloc) ----------
__device__ float g_xs[BSZ*LSEQ*DI];   // in-proj left half
__device__ float g_sz[BSZ*LSEQ*DI];   // silu(z)
__device__ float g_xc[BSZ*LSEQ*DI];   // conv+silu output
__device__ float g_dt[BSZ*LSEQ*DI];   // softplus(dt)
__device__ float g_Bm[BSZ*LSEQ*DS];
__device__ float g_Cm[BSZ*LSEQ*DS];
__device__ float g_ym[BSZ*LSEQ*DI];   // (y + xc*D) * silu(z)

typedef unsigned long long u64;

__device__ __forceinline__ u64 pack2(float lo, float hi) {
    u64 r; asm("mov.b64 %0, {%1, %2};" : "=l"(r) : "f"(lo), "f"(hi)); return r;
}
__device__ __forceinline__ void unpack2(u64 v, float& lo, float& hi) {
    asm("mov.b64 {%0, %1}, %2;" : "=f"(lo), "=f"(hi) : "l"(v));
}
__device__ __forceinline__ u64 fma2(u64 a, u64 b, u64 c) {
    u64 d; asm("fma.rn.f32x2 %0, %1, %2, %3;" : "=l"(d) : "l"(a), "l"(b), "l"(c)); return d;
}
__device__ __forceinline__ float silu_f(float v) { return v / (1.f + __expf(-v)); }

// ============================================================================
// K1: in-projection GEMM.  out[b,l,j] = sum_c x[b,c,l] * W_in[c,j]
// rows = l (tile 64), cols = j (tile 128), k = c (chunks of 16).
// 256 threads, each 4 rows x 4 col-pairs, f32x2 packed FMA.
// j < 256 -> g_xs ; j >= 256 -> g_sz = silu(z)
// ============================================================================
__global__ __launch_bounds__(256) void k_inproj(const float* __restrict__ x,
                                                const float* __restrict__ Win) {
    __shared__ float As[16][64];
    __shared__ float Bs[16][130];
    const int t  = threadIdx.x;
    const int l0 = blockIdx.x * 64, j0 = blockIdx.y * 128, b = blockIdx.z;
    const int ty = t >> 4, tx = t & 15;

    u64 acc[4][4];
#pragma unroll
    for (int i = 0; i < 4; i++)
#pragma unroll
        for (int p = 0; p < 4; p++) acc[i][p] = 0ull;

    const float* xb = x + b * DM * LSEQ;

    for (int c0 = 0; c0 < DM; c0 += 16) {
#pragma unroll
        for (int i = 0; i < 4; i++) {
            int idx = t + i * 256;
            As[idx >> 6][idx & 63] = xb[(c0 + (idx >> 6)) * LSEQ + l0 + (idx & 63)];
        }
#pragma unroll
        for (int i = 0; i < 8; i++) {
            int idx = t + i * 256;
            Bs[idx >> 7][idx & 127] = Win[(c0 + (idx >> 7)) * (2 * DI) + j0 + (idx & 127)];
        }
        __syncthreads();
#pragma unroll
        for (int k = 0; k < 16; k++) {
            float4 av = *(const float4*)&As[k][ty * 4];
            u64 aa[4];
            aa[0] = pack2(av.x, av.x); aa[1] = pack2(av.y, av.y);
            aa[2] = pack2(av.z, av.z); aa[3] = pack2(av.w, av.w);
#pragma unroll
            for (int p = 0; p < 4; p++) {
                float2 bp = *(const float2*)&Bs[k][2 * (tx + 16 * p)];
                u64 bb = pack2(bp.x, bp.y);
#pragma unroll
                for (int i = 0; i < 4; i++) acc[i][p] = fma2(aa[i], bb, acc[i][p]);
            }
        }
        __syncthreads();
    }

    const bool isz = (j0 >= DI);
#pragma unroll
    for (int i = 0; i < 4; i++) {
        int l = l0 + ty * 4 + i;
#pragma unroll
        for (int p = 0; p < 4; p++) {
            float lo, hi; unpack2(acc[i][p], lo, hi);
            int j = j0 + 2 * (tx + 16 * p);
            if (!isz) {
                float2 v; v.x = lo; v.y = hi;
                *(float2*)&g_xs[(b * LSEQ + l) * DI + j] = v;
            } else {
                float2 v; v.x = silu_f(lo); v.y = silu_f(hi);
                *(float2*)&g_sz[(b * LSEQ + l) * DI + (j - DI)] = v;
            }
        }
    }
}

// ============================================================================
// K2: causal depthwise conv(4) + silu -> xc; dbc = xc @ W_x (48);
//     dt = softplus(dbc[:, :16] @ W_dt + b_dt); scatter Bm, Cm.
// One block = 32 sequence rows of one batch. 256 threads.
// ============================================================================
__global__ __launch_bounds__(256) void k_conv_proj(const float* __restrict__ convw,
                                                   const float* __restrict__ convb,
                                                   const float* __restrict__ Wx,
                                                   const float* __restrict__ Wdt,
                                                   const float* __restrict__ bdt) {
    __shared__ float xc_s[32][257];
    __shared__ float dbc_s[32][49];
    const int t  = threadIdx.x;
    const int b  = blockIdx.x >> 7;
    const int l0 = (blockIdx.x & 127) * 32;

    // ---- Phase A: conv + silu (thread t owns channel d = t) ----
    {
        const int d = t;
        const float w0 = convw[d * 4 + 0], w1 = convw[d * 4 + 1];
        const float w2 = convw[d * 4 + 2], w3 = convw[d * 4 + 3];
        const float cb = convb[d];
        const float* pxs = g_xs + b * LSEQ * DI + d;
        float*       pxc = g_xc + b * LSEQ * DI + d;
        float x0, x1, x2;
        if (l0 == 0) { x0 = x1 = x2 = 0.f; }
        else { x0 = pxs[(l0 - 3) * DI]; x1 = pxs[(l0 - 2) * DI]; x2 = pxs[(l0 - 1) * DI]; }
        for (int j = 0; j < 32; j++) {
            float x3 = pxs[(l0 + j) * DI];
            float c  = cb + w0 * x0 + w1 * x1 + w2 * x2 + w3 * x3;
            float s  = silu_f(c);
            xc_s[j][d] = s;
            pxc[(l0 + j) * DI] = s;
            x0 = x1; x1 = x2; x2 = x3;
        }
    }
    __syncthreads();

    // ---- Phase B: dbc[r][0..47] = xc[r] @ W_x ----
    {
        const int r = t & 31, g = t >> 5;   // g in 0..7, 6 cols each
        float acc[6];
#pragma unroll
        for (int jj = 0; jj < 6; jj++) acc[jj] = 0.f;
        const float* wbase = Wx + g * 6;
        for (int c = 0; c < DI; c++) {
            float xv = xc_s[r][c];
            const float2* wp = (const float2*)(wbase + c * 48);
            float2 wa = __ldg(wp), wb = __ldg(wp + 1), wc = __ldg(wp + 2);
            acc[0] = fmaf(xv, wa.x, acc[0]); acc[1] = fmaf(xv, wa.y, acc[1]);
            acc[2] = fmaf(xv, wb.x, acc[2]); acc[3] = fmaf(xv, wb.y, acc[3]);
            acc[4] = fmaf(xv, wc.x, acc[4]); acc[5] = fmaf(xv, wc.y, acc[5]);
        }
#pragma unroll
        for (int jj = 0; jj < 6; jj++) dbc_s[r][g * 6 + jj] = acc[jj];
    }
    __syncthreads();

    // ---- Phase C: dt = softplus(dbc[:, :16] @ W_dt + b_dt) ----
    {
        const int d = t;
        float wdt[16];
#pragma unroll
        for (int k = 0; k < 16; k++) wdt[k] = Wdt[k * DI + d];
        const float bd = bdt[d];
        float* pdt = g_dt + b * LSEQ * DI + d;
        for (int r = 0; r < 32; r++) {
            float a = bd;
#pragma unroll
            for (int k = 0; k < 16; k++) a = fmaf(dbc_s[r][k], wdt[k], a);
            float sp = (a > 20.f) ? a : log1pf(__expf(a));
            pdt[(l0 + r) * DI] = sp;
        }
    }
    // ---- scatter Bm / Cm ----
    for (int i = t; i < 32 * 32; i += 256) {
        int r = i >> 5, c = i & 31;
        float v = dbc_s[r][16 + c];
        int l = l0 + r;
        if (c < 16) g_Bm[(b * LSEQ + l) * DS + c] = v;
        else        g_Cm[(b * LSEQ + l) * DS + (c - 16)] = v;
    }
}

// ============================================================================
// K3: selective scan. warp = 2 channels (half-warp each), lane = state.
// 8-step double-buffered register prefetch; butterfly-shfl y reduction.
// Writes g_ym = (y + xc*D) * silu(z).
// ============================================================================
__global__ __launch_bounds__(64) void k_scan(const float* __restrict__ Alog,
                                             const float* __restrict__ Dvec) {
    const int t = threadIdx.x;
    const int w = blockIdx.x * 2 + (t >> 5);            // 0..255
    const int b = w >> 7;
    const int d = ((w & 127) << 1) | ((t >> 4) & 1);
    const int s = t & 15;
    const float Areg = -__expf(Alog[d * DS + s]);
    const float Dd   = Dvec[d];
    const float* pdt = g_dt + b * LSEQ * DI + d;
    const float* pxc = g_xc + b * LSEQ * DI + d;
    const float* psz = g_sz + b * LSEQ * DI + d;
    const float* pB  = g_Bm + b * LSEQ * DS + s;
    const float* pC  = g_Cm + b * LSEQ * DS + s;
    float*       py  = g_ym + b * LSEQ * DI + d;
    const bool wr = (s == 0);

    float dA[8], xA[8], zA[8], BA[8], CA[8];
    float dB[8], xB[8], zB[8], BB[8], CB[8];
    float h = 0.f;

#pragma unroll
    for (int u = 0; u < 8; u++) {
        dA[u] = pdt[u * DI]; xA[u] = pxc[u * DI]; zA[u] = psz[u * DI];
        BA[u] = pB[u * DS];  CA[u] = pC[u * DS];
    }

    for (int base = 0; base < LSEQ; base += 16) {
        const int l1 = base + 8;
#pragma unroll
        for (int u = 0; u < 8; u++) {
            dB[u] = pdt[(l1 + u) * DI]; xB[u] = pxc[(l1 + u) * DI]; zB[u] = psz[(l1 + u) * DI];
            BB[u] = pB[(l1 + u) * DS];  CB[u] = pC[(l1 + u) * DS];
        }
#pragma unroll
        for (int u = 0; u < 8; u++) {
            float a = __expf(dA[u] * Areg);
            h = fmaf(h, a, dA[u] * xA[u] * BA[u]);
            float v = h * CA[u];
            v += __shfl_xor_sync(0xffffffffu, v, 1, 16);
            v += __shfl_xor_sync(0xffffffffu, v, 2, 16);
            v += __shfl_xor_sync(0xffffffffu, v, 4, 16);
            v += __shfl_xor_sync(0xffffffffu, v, 8, 16);
            if (wr) py[(base + u) * DI] = (v + xA[u] * Dd) * zA[u];
        }
        if (base + 16 < LSEQ) {
            const int l2 = base + 16;
#pragma unroll
            for (int u = 0; u < 8; u++) {
                dA[u] = pdt[(l2 + u) * DI]; xA[u] = pxc[(l2 + u) * DI]; zA[u] = psz[(l2 + u) * DI];
                BA[u] = pB[(l2 + u) * DS];  CA[u] = pC[(l2 + u) * DS];
            }
        }
#pragma unroll
        for (int u = 0; u < 8; u++) {
            float a = __expf(dB[u] * Areg);
            h = fmaf(h, a, dB[u] * xB[u] * BB[u]);
            float v = h * CB[u];
            v += __shfl_xor_sync(0xffffffffu, v, 1, 16);
            v += __shfl_xor_sync(0xffffffffu, v, 2, 16);
            v += __shfl_xor_sync(0xffffffffu, v, 4, 16);
            v += __shfl_xor_sync(0xffffffffu, v, 8, 16);
            if (wr) py[(base + 8 + u) * DI] = (v + xB[u] * Dd) * zB[u];
        }
    }
}

// ============================================================================
// K4: out-projection GEMM.  out[b,c,l] = sum_d ym[b,l,d] * W_out[d,c]
// rows = c (tile 64), cols = l (tile 128), k = d (chunks of 16).
// ============================================================================
__global__ __launch_bounds__(256) void k_outproj(const float* __restrict__ Wout,
                                                 float* __restrict__ out) {
    __shared__ float As[16][64];
    __shared__ float Bs[16][130];
    const int t  = threadIdx.x;
    const int l0 = blockIdx.x * 128, c0 = blockIdx.y * 64, b = blockIdx.z;
    const int ty = t >> 4, tx = t & 15;

    u64 acc[4][4];
#pragma unroll
    for (int i = 0; i < 4; i++)
#pragma unroll
        for (int p = 0; p < 4; p++) acc[i][p] = 0ull;

    for (int d0 = 0; d0 < DI; d0 += 16) {
#pragma unroll
        for (int i = 0; i < 4; i++) {
            int idx = t + i * 256;
            As[idx >> 6][idx & 63] = Wout[(d0 + (idx >> 6)) * DM + c0 + (idx & 63)];
        }
#pragma unroll
        for (int pass = 0; pass < 8; pass++) {
            int ll = pass * 16 + (t >> 4);
            int kk = t & 15;
            Bs[kk][ll] = g_ym[(b * LSEQ + l0 + ll) * DI + d0 + kk];
        }
        __syncthreads();
#pragma unroll
        for (int k = 0; k < 16; k++) {
            float4 av = *(const float4*)&As[k][ty * 4];
            u64 aa[4];
            aa[0] = pack2(av.x, av.x); aa[1] = pack2(av.y, av.y);
            aa[2] = pack2(av.z, av.z); aa[3] = pack2(av.w, av.w);
#pragma unroll
            for (int p = 0; p < 4; p++) {
                float2 bp = *(const float2*)&Bs[k][2 * (tx + 16 * p)];
                u64 bb = pack2(bp.x, bp.y);
#pragma unroll
                for (int i = 0; i < 4; i++) acc[i][p] = fma2(aa[i], bb, acc[i][p]);
            }
        }
        __syncthreads();
    }

#pragma unroll
    for (int i = 0; i < 4; i++) {
        int c = c0 + ty * 4 + i;
#pragma unroll
        for (int p = 0; p < 4; p++) {
            float lo, hi; unpack2(acc[i][p], lo, hi);
            int lc = l0 + 2 * (tx + 16 * p);
            float2 v; v.x = lo; v.y = hi;
            *(float2*)&out[(b * DM + c) * LSEQ + lc] = v;
        }
    }
}

// ============================================================================
extern "C" void kernel_launch(void* const* d_in, const int* in_sizes, int n_in,
                              void* d_out, int out_size) {
    (void)in_sizes; (void)n_in; (void)out_size;
    const float* x     = (const float*)d_in[0];
    const float* Win   = (const float*)d_in[1];
    const float* convw = (const float*)d_in[2];
    const float* convb = (const float*)d_in[3];
    const float* Wx    = (const float*)d_in[4];
    const float* Wdt   = (const float*)d_in[5];
    const float* bdt   = (const float*)d_in[6];
    const float* Alog  = (const float*)d_in[7];
    const float* Dvec  = (const float*)d_in[8];
    const float* Wout  = (const float*)d_in[9];
    float* out = (float*)d_out;

    k_inproj  <<<dim3(64, 4, 2), 256>>>(x, Win);
    k_conv_proj<<<256, 256>>>(convw, convb, Wx, Wdt, bdt);
    k_scan    <<<128, 64>>>(Alog, Dvec);
    k_outproj <<<dim3(32, 4, 2), 256>>>(Wout, out);
}

// round 5
// speedup vs baseline: 1.5425x; 1.5425x over previous
#include <cuda_runtime.h>

#define BSZ  2
#define DM   256
#define LSEQ 4096
#define DI   256
#define DS   16
#define NC   16
#define CHUNK (LSEQ / NC)   // 256

// ---------------- scratch (static device globals; no runtime alloc) ----------
__device__ float g_xs[BSZ*LSEQ*DI];   // in-proj left half          [b][l][d]
__device__ float g_sz[BSZ*LSEQ*DI];   // silu(z)                    [b][l][d]
__device__ float g_xc[BSZ*DI*LSEQ];   // conv+silu output           [b][d][l]
__device__ float g_dt[BSZ*DI*LSEQ];   // softplus(dt)               [b][d][l]
__device__ float g_Bm[BSZ*DS*LSEQ];   // B                          [b][s][l]
__device__ float g_Cm[BSZ*DS*LSEQ];   // C                          [b][s][l]
__device__ float g_ym[BSZ*LSEQ*DI];   // y + xc*D                   [b][l][d]
__device__ float g_S  [BSZ*DI*NC*DS]; // chunk-final local states
__device__ float g_P  [BSZ*DI*NC*DS]; // chunk decay products
__device__ float g_Hin[BSZ*DI*NC*DS]; // chunk initial states

typedef unsigned long long u64;

__device__ __forceinline__ u64 pack2(float lo, float hi) {
    u64 r; asm("mov.b64 %0, {%1, %2};" : "=l"(r) : "f"(lo), "f"(hi)); return r;
}
__device__ __forceinline__ void unpack2(u64 v, float& lo, float& hi) {
    asm("mov.b64 {%0, %1}, %2;" : "=f"(lo), "=f"(hi) : "l"(v));
}
__device__ __forceinline__ u64 fma2(u64 a, u64 b, u64 c) {
    u64 d; asm("fma.rn.f32x2 %0, %1, %2, %3;" : "=l"(d) : "l"(a), "l"(b), "l"(c)); return d;
}
__device__ __forceinline__ float silu_f(float v) { return v / (1.f + __expf(-v)); }

// ============================================================================
// K1: in-projection GEMM.  out[b,l,j] = sum_c x[b,c,l] * W_in[c,j]
// ============================================================================
__global__ __launch_bounds__(256) void k_inproj(const float* __restrict__ x,
                                                const float* __restrict__ Win) {
    __shared__ float As[16][64];
    __shared__ float Bs[16][130];
    const int t  = threadIdx.x;
    const int l0 = blockIdx.x * 64, j0 = blockIdx.y * 128, b = blockIdx.z;
    const int ty = t >> 4, tx = t & 15;

    u64 acc[4][4];
#pragma unroll
    for (int i = 0; i < 4; i++)
#pragma unroll
        for (int p = 0; p < 4; p++) acc[i][p] = 0ull;

    const float* xb = x + b * DM * LSEQ;

    for (int c0 = 0; c0 < DM; c0 += 16) {
#pragma unroll
        for (int i = 0; i < 4; i++) {
            int idx = t + i * 256;
            As[idx >> 6][idx & 63] = xb[(c0 + (idx >> 6)) * LSEQ + l0 + (idx & 63)];
        }
#pragma unroll
        for (int i = 0; i < 8; i++) {
            int idx = t + i * 256;
            Bs[idx >> 7][idx & 127] = Win[(c0 + (idx >> 7)) * (2 * DI) + j0 + (idx & 127)];
        }
        __syncthreads();
#pragma unroll
        for (int k = 0; k < 16; k++) {
            float4 av = *(const float4*)&As[k][ty * 4];
            u64 aa[4];
            aa[0] = pack2(av.x, av.x); aa[1] = pack2(av.y, av.y);
            aa[2] = pack2(av.z, av.z); aa[3] = pack2(av.w, av.w);
#pragma unroll
            for (int p = 0; p < 4; p++) {
                float2 bp = *(const float2*)&Bs[k][2 * (tx + 16 * p)];
                u64 bb = pack2(bp.x, bp.y);
#pragma unroll
                for (int i = 0; i < 4; i++) acc[i][p] = fma2(aa[i], bb, acc[i][p]);
            }
        }
        __syncthreads();
    }

    const bool isz = (j0 >= DI);
#pragma unroll
    for (int i = 0; i < 4; i++) {
        int l = l0 + ty * 4 + i;
#pragma unroll
        for (int p = 0; p < 4; p++) {
            float lo, hi; unpack2(acc[i][p], lo, hi);
            int j = j0 + 2 * (tx + 16 * p);
            if (!isz) {
                float2 v; v.x = lo; v.y = hi;
                *(float2*)&g_xs[(b * LSEQ + l) * DI + j] = v;
            } else {
                float2 v; v.x = silu_f(lo); v.y = silu_f(hi);
                *(float2*)&g_sz[(b * LSEQ + l) * DI + (j - DI)] = v;
            }
        }
    }
}

// ============================================================================
// K2: causal depthwise conv(4) + silu -> xc [d][l]; dbc = xc @ W_x;
//     dt = softplus(dbc[:, :16] @ W_dt + b_dt) -> [d][l]; Bm/Cm -> [s][l].
// One block = 32 sequence rows of one batch. 256 threads.
// ============================================================================
__global__ __launch_bounds__(256) void k_conv_proj(const float* __restrict__ convw,
                                                   const float* __restrict__ convb,
                                                   const float* __restrict__ Wx,
                                                   const float* __restrict__ Wdt,
                                                   const float* __restrict__ bdt) {
    __shared__ float xc_s[32][257];   // reused as dt staging in phase C
    __shared__ float dbc_s[32][49];
    const int t  = threadIdx.x;
    const int b  = blockIdx.x >> 7;
    const int l0 = (blockIdx.x & 127) * 32;

    // ---- Phase A: conv + silu (thread t owns channel d = t) ----
    {
        const int d = t;
        const float w0 = convw[d * 4 + 0], w1 = convw[d * 4 + 1];
        const float w2 = convw[d * 4 + 2], w3 = convw[d * 4 + 3];
        const float cb = convb[d];
        const float* pxs = g_xs + b * LSEQ * DI + d;
        float x0, x1, x2;
        if (l0 == 0) { x0 = x1 = x2 = 0.f; }
        else { x0 = pxs[(l0 - 3) * DI]; x1 = pxs[(l0 - 2) * DI]; x2 = pxs[(l0 - 1) * DI]; }
        for (int j = 0; j < 32; j++) {
            float x3 = pxs[(l0 + j) * DI];
            float c  = cb + w0 * x0 + w1 * x1 + w2 * x2 + w3 * x3;
            xc_s[j][d] = silu_f(c);
            x0 = x1; x1 = x2; x2 = x3;
        }
    }
    __syncthreads();

    // ---- transposed coalesced write of xc to [d][l] ----
    for (int i = t; i < 32 * DI; i += 256) {
        int d2 = i >> 5, r2 = i & 31;
        g_xc[(b * DI + d2) * LSEQ + l0 + r2] = xc_s[r2][d2];
    }

    // ---- Phase B: dbc[r][0..47] = xc[r] @ W_x ----
    {
        const int r = t & 31, g = t >> 5;   // g in 0..7, 6 cols each
        float acc[6];
#pragma unroll
        for (int jj = 0; jj < 6; jj++) acc[jj] = 0.f;
        const float* wbase = Wx + g * 6;
        for (int c = 0; c < DI; c++) {
            float xv = xc_s[r][c];
            const float2* wp = (const float2*)(wbase + c * 48);
            float2 wa = __ldg(wp), wb = __ldg(wp + 1), wc = __ldg(wp + 2);
            acc[0] = fmaf(xv, wa.x, acc[0]); acc[1] = fmaf(xv, wa.y, acc[1]);
            acc[2] = fmaf(xv, wb.x, acc[2]); acc[3] = fmaf(xv, wb.y, acc[3]);
            acc[4] = fmaf(xv, wc.x, acc[4]); acc[5] = fmaf(xv, wc.y, acc[5]);
        }
#pragma unroll
        for (int jj = 0; jj < 6; jj++) dbc_s[r][g * 6 + jj] = acc[jj];
    }
    __syncthreads();   // dbc ready; xc_s reads done -> safe to reuse

    // ---- Phase C: dt = softplus(dbc[:, :16] @ W_dt + b_dt) into xc_s ----
    {
        const int d = t;
        float wdt[16];
#pragma unroll
        for (int k = 0; k < 16; k++) wdt[k] = Wdt[k * DI + d];
        const float bd = bdt[d];
        for (int r = 0; r < 32; r++) {
            float a = bd;
#pragma unroll
            for (int k = 0; k < 16; k++) a = fmaf(dbc_s[r][k], wdt[k], a);
            xc_s[r][d] = (a > 20.f) ? a : log1pf(__expf(a));
        }
    }
    __syncthreads();

    // ---- transposed coalesced write of dt to [d][l] ----
    for (int i = t; i < 32 * DI; i += 256) {
        int d2 = i >> 5, r2 = i & 31;
        g_dt[(b * DI + d2) * LSEQ + l0 + r2] = xc_s[r2][d2];
    }

    // ---- scatter Bm / Cm to [s][l] (coalesced along l) ----
    for (int i = t; i < 32 * 32; i += 256) {
        int c = i >> 5, r = i & 31;
        float v = dbc_s[r][16 + c];
        if (c < 16) g_Bm[(b * DS + c)       * LSEQ + l0 + r] = v;
        else        g_Cm[(b * DS + (c - 16)) * LSEQ + l0 + r] = v;
    }
}

// ============================================================================
// K3a: per-chunk local scan -> S (final h with h0=0) and P = exp(A * sum dt).
// half-warp = one (b,d,chunk); lane = state. 8192 half-warps.
// ============================================================================
__global__ __launch_bounds__(128) void k_scan1(const float* __restrict__ Alog) {
    const int t = threadIdx.x;
    const int hw = blockIdx.x * 8 + (t >> 4);
    const int chunk = hw & (NC - 1);
    const int d = (hw >> 4) & (DI - 1);
    const int b = hw >> 12;
    const int s = t & 15;
    const float Areg = -__expf(Alog[d * DS + s]);
    const int l0 = chunk * CHUNK;
    const float* pdt = g_dt + (b * DI + d) * LSEQ + l0;
    const float* pxc = g_xc + (b * DI + d) * LSEQ + l0;
    const float* pB  = g_Bm + (b * DS + s) * LSEQ + l0;

    float h = 0.f, dts = 0.f;
    float4 dv = *(const float4*)pdt;
    float4 xv = *(const float4*)pxc;
    float4 Bv = *(const float4*)pB;

    for (int l = 0; l < CHUNK; l += 4) {
        float4 dn, xn, Bn;
        if (l + 4 < CHUNK) {
            dn = *(const float4*)(pdt + l + 4);
            xn = *(const float4*)(pxc + l + 4);
            Bn = *(const float4*)(pB  + l + 4);
        }
        h = fmaf(h, __expf(dv.x * Areg), dv.x * xv.x * Bv.x);
        h = fmaf(h, __expf(dv.y * Areg), dv.y * xv.y * Bv.y);
        h = fmaf(h, __expf(dv.z * Areg), dv.z * xv.z * Bv.z);
        h = fmaf(h, __expf(dv.w * Areg), dv.w * xv.w * Bv.w);
        dts += (dv.x + dv.y) + (dv.z + dv.w);
        dv = dn; xv = xn; Bv = Bn;
    }
    const int idx = ((b * DI + d) * NC + chunk) * DS + s;
    g_S[idx] = h;
    g_P[idx] = __expf(Areg * dts);
}

// ============================================================================
// K3b: stitch chunk states. half-warp = one (b,d); serial over chunks.
// ============================================================================
__global__ __launch_bounds__(128) void k_scan2() {
    const int t = threadIdx.x;
    const int hw = blockIdx.x * 8 + (t >> 4);
    const int d = hw & (DI - 1);
    const int b = hw >> 8;
    const int s = t & 15;
    const int base = ((b * DI + d) * NC) * DS + s;
    float H = 0.f;
#pragma unroll
    for (int c = 0; c < NC; c++) {
        g_Hin[base + c * DS] = H;
        H = fmaf(g_P[base + c * DS], H, g_S[base + c * DS]);
    }
}

// ============================================================================
// K3c: per-chunk scan with true initial state; emits ym = y + xc*D  ([l][d]).
// ============================================================================
__global__ __launch_bounds__(128) void k_scan3(const float* __restrict__ Alog,
                                               const float* __restrict__ Dvec) {
    const int t = threadIdx.x;
    const int hw = blockIdx.x * 8 + (t >> 4);
    const int chunk = hw & (NC - 1);
    const int d = (hw >> 4) & (DI - 1);
    const int b = hw >> 12;
    const int s = t & 15;
    const float Areg = -__expf(Alog[d * DS + s]);
    const float Dd = Dvec[d];
    const int l0 = chunk * CHUNK;
    const float* pdt = g_dt + (b * DI + d) * LSEQ + l0;
    const float* pxc = g_xc + (b * DI + d) * LSEQ + l0;
    const float* pB  = g_Bm + (b * DS + s) * LSEQ + l0;
    const float* pC  = g_Cm + (b * DS + s) * LSEQ + l0;
    float*       py  = g_ym + (b * LSEQ + l0) * DI + d;
    const bool wr = (s == 0);

    float h = g_Hin[((b * DI + d) * NC + chunk) * DS + s];

    float4 dv = *(const float4*)pdt;
    float4 xv = *(const float4*)pxc;
    float4 Bv = *(const float4*)pB;
    float4 Cv = *(const float4*)pC;

    for (int l = 0; l < CHUNK; l += 4) {
        float4 dn, xn, Bn, Cn;
        if (l + 4 < CHUNK) {
            dn = *(const float4*)(pdt + l + 4);
            xn = *(const float4*)(pxc + l + 4);
            Bn = *(const float4*)(pB  + l + 4);
            Cn = *(const float4*)(pC  + l + 4);
        }
#define SSTEP(dd, xx, BB, CC, u)                                         \
        {                                                                \
            h = fmaf(h, __expf((dd) * Areg), (dd) * (xx) * (BB));        \
            float v = h * (CC);                                          \
            v += __shfl_xor_sync(0xffffffffu, v, 1, 16);                 \
            v += __shfl_xor_sync(0xffffffffu, v, 2, 16);                 \
            v += __shfl_xor_sync(0xffffffffu, v, 4, 16);                 \
            v += __shfl_xor_sync(0xffffffffu, v, 8, 16);                 \
            if (wr) py[(l + u) * DI] = fmaf((xx), Dd, v);                \
        }
        SSTEP(dv.x, xv.x, Bv.x, Cv.x, 0)
        SSTEP(dv.y, xv.y, Bv.y, Cv.y, 1)
        SSTEP(dv.z, xv.z, Bv.z, Cv.z, 2)
        SSTEP(dv.w, xv.w, Bv.w, Cv.w, 3)
#undef SSTEP
        dv = dn; xv = xn; Bv = Bn; Cv = Cn;
    }
}

// ============================================================================
// K4: out-projection GEMM.  out[b,c,l] = sum_d (ym*sz)[b,l,d] * W_out[d,c]
// ============================================================================
__global__ __launch_bounds__(256) void k_outproj(const float* __restrict__ Wout,
                                                 float* __restrict__ out) {
    __shared__ float As[16][64];
    __shared__ float Bs[16][130];
    const int t  = threadIdx.x;
    const int l0 = blockIdx.x * 128, c0 = blockIdx.y * 64, b = blockIdx.z;
    const int ty = t >> 4, tx = t & 15;

    u64 acc[4][4];
#pragma unroll
    for (int i = 0; i < 4; i++)
#pragma unroll
        for (int p = 0; p < 4; p++) acc[i][p] = 0ull;

    for (int d0 = 0; d0 < DI; d0 += 16) {
#pragma unroll
        for (int i = 0; i < 4; i++) {
            int idx = t + i * 256;
            As[idx >> 6][idx & 63] = Wout[(d0 + (idx >> 6)) * DM + c0 + (idx & 63)];
        }
#pragma unroll
        for (int pass = 0; pass < 8; pass++) {
            int ll = pass * 16 + (t >> 4);
            int kk = t & 15;
            int gidx = (b * LSEQ + l0 + ll) * DI + d0 + kk;
            Bs[kk][ll] = g_ym[gidx] * g_sz[gidx];
        }
        __syncthreads();
#pragma unroll
        for (int k = 0; k < 16; k++) {
            float4 av = *(const float4*)&As[k][ty * 4];
            u64 aa[4];
            aa[0] = pack2(av.x, av.x); aa[1] = pack2(av.y, av.y);
            aa[2] = pack2(av.z, av.z); aa[3] = pack2(av.w, av.w);
#pragma unroll
            for (int p = 0; p < 4; p++) {
                float2 bp = *(const float2*)&Bs[k][2 * (tx + 16 * p)];
                u64 bb = pack2(bp.x, bp.y);
#pragma unroll
                for (int i = 0; i < 4; i++) acc[i][p] = fma2(aa[i], bb, acc[i][p]);
            }
        }
        __syncthreads();
    }

#pragma unroll
    for (int i = 0; i < 4; i++) {
        int c = c0 + ty * 4 + i;
#pragma unroll
        for (int p = 0; p < 4; p++) {
            float lo, hi; unpack2(acc[i][p], lo, hi);
            int lc = l0 + 2 * (tx + 16 * p);
            float2 v; v.x = lo; v.y = hi;
            *(float2*)&out[(b * DM + c) * LSEQ + lc] = v;
        }
    }
}

// ============================================================================
extern "C" void kernel_launch(void* const* d_in, const int* in_sizes, int n_in,
                              void* d_out, int out_size) {
    (void)in_sizes; (void)n_in; (void)out_size;
    const float* x     = (const float*)d_in[0];
    const float* Win   = (const float*)d_in[1];
    const float* convw = (const float*)d_in[2];
    const float* convb = (const float*)d_in[3];
    const float* Wx    = (const float*)d_in[4];
    const float* Wdt   = (const float*)d_in[5];
    const float* bdt   = (const float*)d_in[6];
    const float* Alog  = (const float*)d_in[7];
    const float* Dvec  = (const float*)d_in[8];
    const float* Wout  = (const float*)d_in[9];
    float* out = (float*)d_out;

    k_inproj   <<<dim3(64, 4, 2), 256>>>(x, Win);
    k_conv_proj<<<256, 256>>>(convw, convb, Wx, Wdt, bdt);
    k_scan1    <<<1024, 128>>>(Alog);
    k_scan2    <<<64, 128>>>();
    k_scan3    <<<1024, 128>>>(Alog, Dvec);
    k_outproj  <<<dim3(32, 4, 2), 256>>>(Wout, out);
}

// round 7
// speedup vs baseline: 1.9177x; 1.2432x over previous
#include <cuda_runtime.h>

#define BSZ  2
#define DM   256
#define LSEQ 4096
#define DI   256
#define DS   16
#define NC   16
#define CHUNK (LSEQ / NC)   // 256

// ---------------- scratch (static device globals; no runtime alloc) ----------
__device__ float g_xs [BSZ*LSEQ*DI];   // in-proj left half          [b][l][d]
__device__ float g_sz [BSZ*LSEQ*DI];   // silu(z)                    [b][l][d]
__device__ float g_xc [BSZ*DI*LSEQ];   // conv+silu output           [b][d][l]
__device__ float g_dt [BSZ*DI*LSEQ];   // softplus(dt)               [b][d][l]
__device__ float g_Bm [BSZ*LSEQ*DS];   // B packed  [b][l/4][s][l%4]
__device__ float g_Cm [BSZ*LSEQ*DS];   // C packed  [b][l/4][s][l%4]
__device__ float g_ymT[BSZ*DI*LSEQ];   // (y + xc*D)*silu(z)         [b][d][l]
__device__ float g_S  [BSZ*DI*NC*DS];  // chunk-final local states
__device__ float g_P  [BSZ*DI*NC*DS];  // chunk decay products

typedef unsigned long long u64;

__device__ __forceinline__ u64 pack2(float lo, float hi) {
    u64 r; asm("mov.b64 %0, {%1, %2};" : "=l"(r) : "f"(lo), "f"(hi)); return r;
}
__device__ __forceinline__ void unpack2(u64 v, float& lo, float& hi) {
    asm("mov.b64 {%0, %1}, %2;" : "=f"(lo), "=f"(hi) : "l"(v));
}
__device__ __forceinline__ u64 fma2(u64 a, u64 b, u64 c) {
    u64 d; asm("fma.rn.f32x2 %0, %1, %2, %3;" : "=l"(d) : "l"(a), "l"(b), "l"(c)); return d;
}
__device__ __forceinline__ float silu_f(float v) { return v / (1.f + __expf(-v)); }

__device__ __forceinline__ void cp_async16(void* smem, const void* g) {
    unsigned sa = (unsigned)__cvta_generic_to_shared(smem);
    asm volatile("cp.async.cg.shared.global [%0], [%1], 16;\n" :: "r"(sa), "l"(g));
}
__device__ __forceinline__ void cp_commit() {
    asm volatile("cp.async.commit_group;\n");
}
__device__ __forceinline__ void cp_wait0() {
    asm volatile("cp.async.wait_group 0;\n");
}

// ============================================================================
// K1: in-projection GEMM.  out[b,l,j] = sum_c x[b,c,l] * W_in[c,j]
// 64(l) x 128(j) tiles, K-tiles of 16, cp.async double-buffered.
// ============================================================================
__global__ __launch_bounds__(256) void k_inproj(const float* __restrict__ x,
                                                const float* __restrict__ Win) {
    __shared__ float As[2][16][64];
    __shared__ float Bs[2][16][132];
    const int t  = threadIdx.x;
    const int l0 = blockIdx.x * 64, j0 = blockIdx.y * 128, b = blockIdx.z;
    const int ty = t >> 4, tx = t & 15;
    const float* xb = x + b * DM * LSEQ;

    u64 acc[4][4];
#pragma unroll
    for (int i = 0; i < 4; i++)
#pragma unroll
        for (int p = 0; p < 4; p++) acc[i][p] = 0ull;

    // prefetch helpers
    const int ka = t >> 4, ja = (t & 15) * 4;                 // A: 16x64
    auto pref = [&](int tile, int buf) {
        cp_async16(&As[buf][ka][ja], xb + (tile * 16 + ka) * LSEQ + l0 + ja);
#pragma unroll
        for (int i = 0; i < 2; i++) {
            int idx = t + i * 256;
            int kb = idx >> 5, jb = (idx & 31) * 4;
            cp_async16(&Bs[buf][kb][jb], Win + (tile * 16 + kb) * (2 * DI) + j0 + jb);
        }
    };

    pref(0, 0); cp_commit();

    for (int it = 0; it < 16; it++) {
        const int buf = it & 1;
        cp_wait0();
        __syncthreads();
        if (it + 1 < 16) { pref(it + 1, buf ^ 1); cp_commit(); }
#pragma unroll
        for (int k = 0; k < 16; k++) {
            float4 av = *(const float4*)&As[buf][k][ty * 4];
            u64 aa[4];
            aa[0] = pack2(av.x, av.x); aa[1] = pack2(av.y, av.y);
            aa[2] = pack2(av.z, av.z); aa[3] = pack2(av.w, av.w);
#pragma unroll
            for (int p = 0; p < 4; p++) {
                float2 bp = *(const float2*)&Bs[buf][k][2 * (tx + 16 * p)];
                u64 bb = pack2(bp.x, bp.y);
#pragma unroll
                for (int i = 0; i < 4; i++) acc[i][p] = fma2(aa[i], bb, acc[i][p]);
            }
        }
        __syncthreads();
    }

    const bool isz = (j0 >= DI);
#pragma unroll
    for (int i = 0; i < 4; i++) {
        int l = l0 + ty * 4 + i;
#pragma unroll
        for (int p = 0; p < 4; p++) {
            float lo, hi; unpack2(acc[i][p], lo, hi);
            int j = j0 + 2 * (tx + 16 * p);
            if (!isz) {
                float2 v; v.x = lo; v.y = hi;
                *(float2*)&g_xs[(b * LSEQ + l) * DI + j] = v;
            } else {
                float2 v; v.x = silu_f(lo); v.y = silu_f(hi);
                *(float2*)&g_sz[(b * LSEQ + l) * DI + (j - DI)] = v;
            }
        }
    }
}

// ============================================================================
// K2: causal depthwise conv(4) + silu -> xc [d][l]; dbc = xc @ W_x;
//     dt = softplus(dbc[:, :16] @ W_dt + b_dt) -> [d][l];
//     B/C packed [l/4][s][l%4].
// One block = 32 sequence rows of one batch. 256 threads.
// ============================================================================
__global__ __launch_bounds__(256) void k_conv_proj(const float* __restrict__ convw,
                                                   const float* __restrict__ convb,
                                                   const float* __restrict__ Wx,
                                                   const float* __restrict__ Wdt,
                                                   const float* __restrict__ bdt) {
    __shared__ float xc_s[32][257];   // reused as dt staging in phase C
    __shared__ float dbc_s[32][49];
    const int t  = threadIdx.x;
    const int b  = blockIdx.x >> 7;
    const int l0 = (blockIdx.x & 127) * 32;

    // ---- Phase A: conv + silu (thread t owns channel d = t) ----
    {
        const int d = t;
        const float w0 = convw[d * 4 + 0], w1 = convw[d * 4 + 1];
        const float w2 = convw[d * 4 + 2], w3 = convw[d * 4 + 3];
        const float cb = convb[d];
        const float* pxs = g_xs + b * LSEQ * DI + d;
        float x0, x1, x2;
        if (l0 == 0) { x0 = x1 = x2 = 0.f; }
        else { x0 = pxs[(l0 - 3) * DI]; x1 = pxs[(l0 - 2) * DI]; x2 = pxs[(l0 - 1) * DI]; }
        for (int j = 0; j < 32; j++) {
            float x3 = pxs[(l0 + j) * DI];
            float c  = cb + w0 * x0 + w1 * x1 + w2 * x2 + w3 * x3;
            xc_s[j][d] = silu_f(c);
            x0 = x1; x1 = x2; x2 = x3;
        }
    }
    __syncthreads();

    // ---- transposed coalesced write of xc to [d][l] ----
    for (int i = t; i < 32 * DI; i += 256) {
        int d2 = i >> 5, r2 = i & 31;
        g_xc[(b * DI + d2) * LSEQ + l0 + r2] = xc_s[r2][d2];
    }

    // ---- Phase B: dbc[r][0..47] = xc[r] @ W_x ----
    {
        const int r = t & 31, g = t >> 5;   // g in 0..7, 6 cols each
        float acc[6];
#pragma unroll
        for (int jj = 0; jj < 6; jj++) acc[jj] = 0.f;
        const float* wbase = Wx + g * 6;
        for (int c = 0; c < DI; c++) {
            float xv = xc_s[r][c];
            const float2* wp = (const float2*)(wbase + c * 48);
            float2 wa = __ldg(wp), wb = __ldg(wp + 1), wc = __ldg(wp + 2);
            acc[0] = fmaf(xv, wa.x, acc[0]); acc[1] = fmaf(xv, wa.y, acc[1]);
            acc[2] = fmaf(xv, wb.x, acc[2]); acc[3] = fmaf(xv, wb.y, acc[3]);
            acc[4] = fmaf(xv, wc.x, acc[4]); acc[5] = fmaf(xv, wc.y, acc[5]);
        }
#pragma unroll
        for (int jj = 0; jj < 6; jj++) dbc_s[r][g * 6 + jj] = acc[jj];
    }
    __syncthreads();   // dbc ready; xc_s reads done -> safe to reuse

    // ---- Phase C: dt = softplus(dbc[:, :16] @ W_dt + b_dt) into xc_s ----
    {
        const int d = t;
        float wdt[16];
#pragma unroll
        for (int k = 0; k < 16; k++) wdt[k] = Wdt[k * DI + d];
        const float bd = bdt[d];
        for (int r = 0; r < 32; r++) {
            float a = bd;
#pragma unroll
            for (int k = 0; k < 16; k++) a = fmaf(dbc_s[r][k], wdt[k], a);
            xc_s[r][d] = (a > 20.f) ? a : log1pf(__expf(a));
        }
    }
    __syncthreads();

    // ---- transposed coalesced write of dt to [d][l] ----
    for (int i = t; i < 32 * DI; i += 256) {
        int d2 = i >> 5, r2 = i & 31;
        g_dt[(b * DI + d2) * LSEQ + l0 + r2] = xc_s[r2][d2];
    }

    // ---- packed coalesced write of B / C: [l/4][s][l%4] ----
    {
        const int base = (b * LSEQ + l0) * DS;  // == ((b*LSEQ+l0)>>2)*64
        for (int i = t; i < 32 * DS; i += 256) {
            int g4 = i >> 6, s = (i >> 2) & 15, r2 = i & 3;
            int r = g4 * 4 + r2;
            g_Bm[base + i] = dbc_s[r][16 + s];
            g_Cm[base + i] = dbc_s[r][32 + s];
        }
    }
}

// ============================================================================
// K3a: per-chunk local scan -> S (final h with h0=0) and P = exp(A * sum dt).
// half-warp = one (b,d,chunk); lane = state. 8192 half-warps.
// ============================================================================
__global__ __launch_bounds__(128) void k_scan1(const float* __restrict__ Alog) {
    const int t = threadIdx.x;
    const int hw = blockIdx.x * 8 + (t >> 4);
    const int chunk = hw & (NC - 1);
    const int d = (hw >> 4) & (DI - 1);
    const int b = hw >> 12;
    const int s = t & 15;
    const float Areg = -__expf(Alog[d * DS + s]);
    const int l0 = chunk * CHUNK;
    const float* pdt = g_dt + (b * DI + d) * LSEQ + l0;
    const float* pxc = g_xc + (b * DI + d) * LSEQ + l0;
    const float* pB4 = g_Bm + (b * LSEQ + l0) * DS + s * 4;

    float h = 0.f, dts = 0.f;
    float4 dv = *(const float4*)pdt;
    float4 xv = *(const float4*)pxc;
    float4 Bv = *(const float4*)pB4;

    for (int l = 0; l < CHUNK; l += 4) {
        float4 dn, xn, Bn;
        if (l + 4 < CHUNK) {
            dn = *(const float4*)(pdt + l + 4);
            xn = *(const float4*)(pxc + l + 4);
            Bn = *(const float4*)(pB4 + (l >> 2) * 64 + 64);
        }
        h = fmaf(h, __expf(dv.x * Areg), dv.x * xv.x * Bv.x);
        h = fmaf(h, __expf(dv.y * Areg), dv.y * xv.y * Bv.y);
        h = fmaf(h, __expf(dv.z * Areg), dv.z * xv.z * Bv.z);
        h = fmaf(h, __expf(dv.w * Areg), dv.w * xv.w * Bv.w);
        dts += (dv.x + dv.y) + (dv.z + dv.w);
        dv = dn; xv = xn; Bv = Bn;
    }
    const int idx = ((b * DI + d) * NC + chunk) * DS + s;
    g_S[idx] = h;
    g_P[idx] = __expf(Areg * dts);
}

// ============================================================================
// K3b: per-chunk scan with true initial state (self-stitched prefix);
// emits g_ymT = (y + xc*D) * silu(z)   in [b][d][l] layout.
// ============================================================================
__global__ __launch_bounds__(128) void k_scan3(const float* __restrict__ Alog,
                                               const float* __restrict__ Dvec) {
    const int t = threadIdx.x;
    const int hw = blockIdx.x * 8 + (t >> 4);
    const int chunk = hw & (NC - 1);
    const int d = (hw >> 4) & (DI - 1);
    const int b = hw >> 12;
    const int s = t & 15;
    const float Areg = -__expf(Alog[d * DS + s]);
    const float Dd = Dvec[d];
    const int l0 = chunk * CHUNK;
    const float* pdt = g_dt + (b * DI + d) * LSEQ + l0;
    const float* pxc = g_xc + (b * DI + d) * LSEQ + l0;
    const float* pB4 = g_Bm + (b * LSEQ + l0) * DS + s * 4;
    const float* pC4 = g_Cm + (b * LSEQ + l0) * DS + s * 4;
    const float* psz = g_sz + (b * LSEQ + l0) * DI + d;
    float*       pyT = g_ymT + (b * DI + d) * LSEQ + l0;
    const bool wr = (s == 0);

    // ---- self-stitched prefix: initial state for this chunk ----
    float h = 0.f;
    {
        const int pbase = (b * DI + d) * NC * DS + s;
#pragma unroll
        for (int c = 0; c < NC - 1; c++) {
            if (c < chunk) h = fmaf(g_P[pbase + c * DS], h, g_S[pbase + c * DS]);
        }
    }

    float4 dv = *(const float4*)pdt;
    float4 xv = *(const float4*)pxc;
    float4 Bv = *(const float4*)pB4;
    float4 Cv = *(const float4*)pC4;

    for (int l = 0; l < CHUNK; l += 4) {
        float4 dn, xn, Bn, Cn;
        if (l + 4 < CHUNK) {
            dn = *(const float4*)(pdt + l + 4);
            xn = *(const float4*)(pxc + l + 4);
            Bn = *(const float4*)(pB4 + (l >> 2) * 64 + 64);
            Cn = *(const float4*)(pC4 + (l >> 2) * 64 + 64);
        }
#define SSTEP(dd, xx, BB, CC, u)                                         \
        {                                                                \
            h = fmaf(h, __expf((dd) * Areg), (dd) * (xx) * (BB));        \
            float v = h * (CC);                                          \
            v += __shfl_xor_sync(0xffffffffu, v, 1, 16);                 \
            v += __shfl_xor_sync(0xffffffffu, v, 2, 16);                 \
            v += __shfl_xor_sync(0xffffffffu, v, 4, 16);                 \
            v += __shfl_xor_sync(0xffffffffu, v, 8, 16);                 \
            if (wr) pyT[l + u] = fmaf((xx), Dd, v) * psz[(l + u) * DI];  \
        }
        SSTEP(dv.x, xv.x, Bv.x, Cv.x, 0)
        SSTEP(dv.y, xv.y, Bv.y, Cv.y, 1)
        SSTEP(dv.z, xv.z, Bv.z, Cv.z, 2)
        SSTEP(dv.w, xv.w, Bv.w, Cv.w, 3)
#undef SSTEP
        dv = dn; xv = xn; Bv = Bn; Cv = Cn;
    }
}

// ============================================================================
// K4: out-projection GEMM.  out[b,c,l] = sum_d ymT[b,d,l] * W_out[d,c]
// 64(c) x 128(l) tiles, K-tiles of 16 over d, cp.async double-buffered.
// ============================================================================
__global__ __launch_bounds__(256) void k_outproj(const float* __restrict__ Wout,
                                                 float* __restrict__ out) {
    __shared__ float As[2][16][64];
    __shared__ float Bs[2][16][132];
    const int t  = threadIdx.x;
    const int l0 = blockIdx.x * 128, c0 = blockIdx.y * 64, b = blockIdx.z;
    const int ty = t >> 4, tx = t & 15;

    u64 acc[4][4];
#pragma unroll
    for (int i = 0; i < 4; i++)
#pragma unroll
        for (int p = 0; p < 4; p++) acc[i][p] = 0ull;

    const float* ymb = g_ymT + b * DI * LSEQ;
    const int ka = t >> 4, ca = (t & 15) * 4;
    auto pref = [&](int tile, int buf) {
        cp_async16(&As[buf][ka][ca], Wout + (tile * 16 + ka) * DM + c0 + ca);
#pragma unroll
        for (int i = 0; i < 2; i++) {
            int idx = t + i * 256;
            int kb = idx >> 5, lb = (idx & 31) * 4;
            cp_async16(&Bs[buf][kb][lb], ymb + (tile * 16 + kb) * LSEQ + l0 + lb);
        }
    };

    pref(0, 0); cp_commit();

    for (int it = 0; it < 16; it++) {
        const int buf = it & 1;
        cp_wait0();
        __syncthreads();
        if (it + 1 < 16) { pref(it + 1, buf ^ 1); cp_commit(); }
#pragma unroll
        for (int k = 0; k < 16; k++) {
            float4 av = *(const float4*)&As[buf][k][ty * 4];
            u64 aa[4];
            aa[0] = pack2(av.x, av.x); aa[1] = pack2(av.y, av.y);
            aa[2] = pack2(av.z, av.z); aa[3] = pack2(av.w, av.w);
#pragma unroll
            for (int p = 0; p < 4; p++) {
                float2 bp = *(const float2*)&Bs[buf][k][2 * (tx + 16 * p)];
                u64 bb = pack2(bp.x, bp.y);
#pragma unroll
                for (int i = 0; i < 4; i++) acc[i][p] = fma2(aa[i], bb, acc[i][p]);
            }
        }
        __syncthreads();
    }

#pragma unroll
    for (int i = 0; i < 4; i++) {
        int c = c0 + ty * 4 + i;
#pragma unroll
        for (int p = 0; p < 4; p++) {
            float lo, hi; unpack2(acc[i][p], lo, hi);
            int lc = l0 + 2 * (tx + 16 * p);
            float2 v; v.x = lo; v.y = hi;
            *(float2*)&out[(b * DM + c) * LSEQ + lc] = v;
        }
    }
}

// ============================================================================
extern "C" void kernel_launch(void* const* d_in, const int* in_sizes, int n_in,
                              void* d_out, int out_size) {
    (void)in_sizes; (void)n_in; (void)out_size;
    const float* x     = (const float*)d_in[0];
    const float* Win   = (const float*)d_in[1];
    const float* convw = (const float*)d_in[2];
    const float* convb = (const float*)d_in[3];
    const float* Wx    = (const float*)d_in[4];
    const float* Wdt   = (const float*)d_in[5];
    const float* bdt   = (const float*)d_in[6];
    const float* Alog  = (const float*)d_in[7];
    const float* Dvec  = (const float*)d_in[8];
    const float* Wout  = (const float*)d_in[9];
    float* out = (float*)d_out;

    k_inproj   <<<dim3(64, 4, 2), 256>>>(x, Win);
    k_conv_proj<<<256, 256>>>(convw, convb, Wx, Wdt, bdt);
    k_scan1    <<<1024, 128>>>(Alog);
    k_scan3    <<<1024, 128>>>(Alog, Dvec);
    k_outproj  <<<dim3(32, 4, 2), 256>>>(Wout, out);
}

// round 9
// speedup vs baseline: 2.6181x; 1.3653x over previous
#include <cuda_runtime.h>

#define BSZ  2
#define DM   256
#define LSEQ 4096
#define DI   256
#define DS   16
#define NC   16
#define CHUNK (LSEQ / NC)   // 256

// ---------------- scratch (static device globals; no runtime alloc) ----------
__device__ float g_xs [BSZ*LSEQ*DI];   // in-proj left half          [b][l][d]
__device__ float g_szT[BSZ*DI*LSEQ];   // silu(z) TRANSPOSED         [b][d][l]
__device__ float g_xc [BSZ*DI*LSEQ];   // conv+silu output           [b][d][l]
__device__ float g_dt [BSZ*DI*LSEQ];   // softplus(dt)               [b][d][l]
__device__ float g_Bm [BSZ*LSEQ*DS];   // B packed  [b][l/4][s][l%4]
__device__ float g_Cm [BSZ*LSEQ*DS];   // C packed  [b][l/4][s][l%4]
__device__ float g_ymT[BSZ*DI*LSEQ];   // (y + xc*D)*silu(z)         [b][d][l]
__device__ float g_S  [BSZ*DI*NC*DS];  // chunk-final local states
__device__ float g_P  [BSZ*DI*NC*DS];  // chunk decay products

typedef unsigned long long u64;

__device__ __forceinline__ u64 pack2(float lo, float hi) {
    u64 r; asm("mov.b64 %0, {%1, %2};" : "=l"(r) : "f"(lo), "f"(hi)); return r;
}
__device__ __forceinline__ void unpack2(u64 v, float& lo, float& hi) {
    asm("mov.b64 {%0, %1}, %2;" : "=f"(lo), "=f"(hi) : "l"(v));
}
__device__ __forceinline__ u64 fma2(u64 a, u64 b, u64 c) {
    u64 d; asm("fma.rn.f32x2 %0, %1, %2, %3;" : "=l"(d) : "l"(a), "l"(b), "l"(c)); return d;
}
__device__ __forceinline__ float silu_f(float v) { return v / (1.f + __expf(-v)); }

__device__ __forceinline__ void cp_async16(void* smem, const void* g) {
    unsigned sa = (unsigned)__cvta_generic_to_shared(smem);
    asm volatile("cp.async.cg.shared.global [%0], [%1], 16;\n" :: "r"(sa), "l"(g));
}
__device__ __forceinline__ void cp_commit() {
    asm volatile("cp.async.commit_group;\n");
}
__device__ __forceinline__ void cp_wait0() {
    asm volatile("cp.async.wait_group 0;\n");
}

// Exchange-halving butterfly: reduce 16 independent sums (w[j], one per step)
// across the 16 lanes of a half-warp. 15 shuffles total. Result for step j
// lands in lane j (returned in w[0] of lane s=j).
__device__ __forceinline__ float hreduce16(float* w, int s) {
#pragma unroll
    for (int i = 0; i < 8; i++) {
        float snd = (s & 8) ? w[i] : w[i + 8];
        float kp  = (s & 8) ? w[i + 8] : w[i];
        w[i] = kp + __shfl_xor_sync(0xffffffffu, snd, 8, 16);
    }
#pragma unroll
    for (int i = 0; i < 4; i++) {
        float snd = (s & 4) ? w[i] : w[i + 4];
        float kp  = (s & 4) ? w[i + 4] : w[i];
        w[i] = kp + __shfl_xor_sync(0xffffffffu, snd, 4, 16);
    }
#pragma unroll
    for (int i = 0; i < 2; i++) {
        float snd = (s & 2) ? w[i] : w[i + 2];
        float kp  = (s & 2) ? w[i + 2] : w[i];
        w[i] = kp + __shfl_xor_sync(0xffffffffu, snd, 2, 16);
    }
    {
        float snd = (s & 1) ? w[0] : w[1];
        float kp  = (s & 1) ? w[1] : w[0];
        w[0] = kp + __shfl_xor_sync(0xffffffffu, snd, 1, 16);
    }
    return w[0];
}

// ============================================================================
// K1: in-projection GEMM.  out[b,l,j] = sum_c x[b,c,l] * W_in[c,j]
// 64(l) x 128(j) tiles, K-tiles of 16, cp.async double-buffered.
// xs half -> [b][l][d]; z half -> silu -> TRANSPOSED [b][d][l].
// ============================================================================
__global__ __launch_bounds__(256) void k_inproj(const float* __restrict__ x,
                                                const float* __restrict__ Win) {
    __shared__ float As[2][16][64];
    __shared__ float Bs[2][16][132];
    const int t  = threadIdx.x;
    const int l0 = blockIdx.x * 64, j0 = blockIdx.y * 128, b = blockIdx.z;
    const int ty = t >> 4, tx = t & 15;
    const float* xb = x + b * DM * LSEQ;

    u64 acc[4][4];
#pragma unroll
    for (int i = 0; i < 4; i++)
#pragma unroll
        for (int p = 0; p < 4; p++) acc[i][p] = 0ull;

    const int ka = t >> 4, ja = (t & 15) * 4;                 // A: 16x64
    auto pref = [&](int tile, int buf) {
        cp_async16(&As[buf][ka][ja], xb + (tile * 16 + ka) * LSEQ + l0 + ja);
#pragma unroll
        for (int i = 0; i < 2; i++) {
            int idx = t + i * 256;
            int kb = idx >> 5, jb = (idx & 31) * 4;
            cp_async16(&Bs[buf][kb][jb], Win + (tile * 16 + kb) * (2 * DI) + j0 + jb);
        }
    };

    pref(0, 0); cp_commit();

    for (int it = 0; it < 16; it++) {
        const int buf = it & 1;
        cp_wait0();
        __syncthreads();
        if (it + 1 < 16) { pref(it + 1, buf ^ 1); cp_commit(); }
#pragma unroll
        for (int k = 0; k < 16; k++) {
            float4 av = *(const float4*)&As[buf][k][ty * 4];
            u64 aa[4];
            aa[0] = pack2(av.x, av.x); aa[1] = pack2(av.y, av.y);
            aa[2] = pack2(av.z, av.z); aa[3] = pack2(av.w, av.w);
#pragma unroll
            for (int p = 0; p < 4; p++) {
                float2 bp = *(const float2*)&Bs[buf][k][2 * (tx + 16 * p)];
                u64 bb = pack2(bp.x, bp.y);
#pragma unroll
                for (int i = 0; i < 4; i++) acc[i][p] = fma2(aa[i], bb, acc[i][p]);
            }
        }
        __syncthreads();
    }

    if (j0 < DI) {
#pragma unroll
        for (int i = 0; i < 4; i++) {
            int l = l0 + ty * 4 + i;
#pragma unroll
            for (int p = 0; p < 4; p++) {
                float lo, hi; unpack2(acc[i][p], lo, hi);
                int j = j0 + 2 * (tx + 16 * p);
                float2 v; v.x = lo; v.y = hi;
                *(float2*)&g_xs[(b * LSEQ + l) * DI + j] = v;
            }
        }
    } else {
        // z half: silu + transposed store [d][l]
        float lv[4][4], hv[4][4];
#pragma unroll
        for (int i = 0; i < 4; i++)
#pragma unroll
            for (int p = 0; p < 4; p++) unpack2(acc[i][p], lv[i][p], hv[i][p]);
#pragma unroll
        for (int p = 0; p < 4; p++) {
            int jbase = (j0 - DI) + 2 * (tx + 16 * p);
            float4 v0, v1;
            v0.x = silu_f(lv[0][p]); v0.y = silu_f(lv[1][p]);
            v0.z = silu_f(lv[2][p]); v0.w = silu_f(lv[3][p]);
            v1.x = silu_f(hv[0][p]); v1.y = silu_f(hv[1][p]);
            v1.z = silu_f(hv[2][p]); v1.w = silu_f(hv[3][p]);
            *(float4*)&g_szT[(b * DI + jbase)     * LSEQ + l0 + ty * 4] = v0;
            *(float4*)&g_szT[(b * DI + jbase + 1) * LSEQ + l0 + ty * 4] = v1;
        }
    }
}

// ============================================================================
// K2: causal depthwise conv(4) + silu -> xc [d][l]; dbc = xc @ W_x;
//     dt = softplus(dbc[:, :16] @ W_dt + b_dt) -> [d][l];
//     B/C packed [l/4][s][l%4].
// ============================================================================
__global__ __launch_bounds__(256) void k_conv_proj(const float* __restrict__ convw,
                                                   const float* __restrict__ convb,
                                                   const float* __restrict__ Wx,
                                                   const float* __restrict__ Wdt,
                                                   const float* __restrict__ bdt) {
    __shared__ float xc_s[32][257];   // reused as dt staging in phase C
    __shared__ float dbc_s[32][49];
    const int t  = threadIdx.x;
    const int b  = blockIdx.x >> 7;
    const int l0 = (blockIdx.x & 127) * 32;

    // ---- Phase A: conv + silu (thread t owns channel d = t) ----
    {
        const int d = t;
        const float w0 = convw[d * 4 + 0], w1 = convw[d * 4 + 1];
        const float w2 = convw[d * 4 + 2], w3 = convw[d * 4 + 3];
        const float cb = convb[d];
        const float* pxs = g_xs + b * LSEQ * DI + d;
        float x0, x1, x2;
        if (l0 == 0) { x0 = x1 = x2 = 0.f; }
        else { x0 = pxs[(l0 - 3) * DI]; x1 = pxs[(l0 - 2) * DI]; x2 = pxs[(l0 - 1) * DI]; }
        for (int j = 0; j < 32; j++) {
            float x3 = pxs[(l0 + j) * DI];
            float c  = cb + w0 * x0 + w1 * x1 + w2 * x2 + w3 * x3;
            xc_s[j][d] = silu_f(c);
            x0 = x1; x1 = x2; x2 = x3;
        }
    }
    __syncthreads();

    // ---- transposed coalesced write of xc to [d][l] ----
    for (int i = t; i < 32 * DI; i += 256) {
        int d2 = i >> 5, r2 = i & 31;
        g_xc[(b * DI + d2) * LSEQ + l0 + r2] = xc_s[r2][d2];
    }

    // ---- Phase B: dbc[r][0..47] = xc[r] @ W_x ----
    {
        const int r = t & 31, g = t >> 5;   // g in 0..7, 6 cols each
        float acc[6];
#pragma unroll
        for (int jj = 0; jj < 6; jj++) acc[jj] = 0.f;
        const float* wbase = Wx + g * 6;
        for (int c = 0; c < DI; c++) {
            float xv = xc_s[r][c];
            const float2* wp = (const float2*)(wbase + c * 48);
            float2 wa = __ldg(wp), wb = __ldg(wp + 1), wc = __ldg(wp + 2);
            acc[0] = fmaf(xv, wa.x, acc[0]); acc[1] = fmaf(xv, wa.y, acc[1]);
            acc[2] = fmaf(xv, wb.x, acc[2]); acc[3] = fmaf(xv, wb.y, acc[3]);
            acc[4] = fmaf(xv, wc.x, acc[4]); acc[5] = fmaf(xv, wc.y, acc[5]);
        }
#pragma unroll
        for (int jj = 0; jj < 6; jj++) dbc_s[r][g * 6 + jj] = acc[jj];
    }
    __syncthreads();

    // ---- Phase C: dt = softplus(dbc[:, :16] @ W_dt + b_dt) into xc_s ----
    {
        const int d = t;
        float wdt[16];
#pragma unroll
        for (int k = 0; k < 16; k++) wdt[k] = Wdt[k * DI + d];
        const float bd = bdt[d];
        for (int r = 0; r < 32; r++) {
            float a = bd;
#pragma unroll
            for (int k = 0; k < 16; k++) a = fmaf(dbc_s[r][k], wdt[k], a);
            xc_s[r][d] = (a > 20.f) ? a : log1pf(__expf(a));
        }
    }
    __syncthreads();

    // ---- transposed coalesced write of dt to [d][l] ----
    for (int i = t; i < 32 * DI; i += 256) {
        int d2 = i >> 5, r2 = i & 31;
        g_dt[(b * DI + d2) * LSEQ + l0 + r2] = xc_s[r2][d2];
    }

    // ---- packed coalesced write of B / C: [l/4][s][l%4] ----
    {
        const int base = (b * LSEQ + l0) * DS;
        for (int i = t; i < 32 * DS; i += 256) {
            int g4 = i >> 6, s = (i >> 2) & 15, r2 = i & 3;
            int r = g4 * 4 + r2;
            g_Bm[base + i] = dbc_s[r][16 + s];
            g_Cm[base + i] = dbc_s[r][32 + s];
        }
    }
}

// ============================================================================
// K3a: per-chunk local scan -> S (final h with h0=0) and P = exp(A * sum dt).
// half-warp = one (b,d,chunk); lane = state. 8192 half-warps.
// ============================================================================
__global__ __launch_bounds__(128) void k_scan1(const float* __restrict__ Alog) {
    const int t = threadIdx.x;
    const int hw = blockIdx.x * 8 + (t >> 4);
    const int chunk = hw & (NC - 1);
    const int d = (hw >> 4) & (DI - 1);
    const int b = hw >> 12;
    const int s = t & 15;
    const float Areg = -__expf(Alog[d * DS + s]);
    const int l0 = chunk * CHUNK;
    const float* pdt = g_dt + (b * DI + d) * LSEQ + l0;
    const float* pxc = g_xc + (b * DI + d) * LSEQ + l0;
    const float* pB4 = g_Bm + (b * LSEQ + l0) * DS + s * 4;

    float h = 0.f, dts = 0.f;
    float4 dv = *(const float4*)pdt;
    float4 xv = *(const float4*)pxc;
    float4 Bv = *(const float4*)pB4;

    for (int l = 0; l < CHUNK; l += 4) {
        float4 dn, xn, Bn;
        if (l + 4 < CHUNK) {
            dn = *(const float4*)(pdt + l + 4);
            xn = *(const float4*)(pxc + l + 4);
            Bn = *(const float4*)(pB4 + (l >> 2) * 64 + 64);
        }
        h = fmaf(h, __expf(dv.x * Areg), dv.x * xv.x * Bv.x);
        h = fmaf(h, __expf(dv.y * Areg), dv.y * xv.y * Bv.y);
        h = fmaf(h, __expf(dv.z * Areg), dv.z * xv.z * Bv.z);
        h = fmaf(h, __expf(dv.w * Areg), dv.w * xv.w * Bv.w);
        dts += (dv.x + dv.y) + (dv.z + dv.w);
        dv = dn; xv = xn; Bv = Bn;
    }
    const int idx = ((b * DI + d) * NC + chunk) * DS + s;
    g_S[idx] = h;
    g_P[idx] = __expf(Areg * dts);
}

// ============================================================================
// K3b: per-chunk scan with true initial state (self-stitched prefix).
// Reduction batched over 16 steps via exchange-halving butterfly (15 shfl).
// Emits g_ymT = (y + xc*D) * silu(z)   in [b][d][l] layout (coalesced store).
// ============================================================================
__global__ __launch_bounds__(128) void k_scan3(const float* __restrict__ Alog,
                                               const float* __restrict__ Dvec) {
    const int t = threadIdx.x;
    const int hw = blockIdx.x * 8 + (t >> 4);
    const int chunk = hw & (NC - 1);
    const int d = (hw >> 4) & (DI - 1);
    const int b = hw >> 12;
    const int s = t & 15;
    const float Areg = -__expf(Alog[d * DS + s]);
    const float Dd = Dvec[d];
    const int l0 = chunk * CHUNK;
    const float* pdt = g_dt  + (b * DI + d) * LSEQ + l0;
    const float* pxc = g_xc  + (b * DI + d) * LSEQ + l0;
    const float* psz = g_szT + (b * DI + d) * LSEQ + l0;
    const float* pB4 = g_Bm  + (b * LSEQ + l0) * DS + s * 4;
    const float* pC4 = g_Cm  + (b * LSEQ + l0) * DS + s * 4;
    float*       pyT = g_ymT + (b * DI + d) * LSEQ + l0;

    // ---- self-stitched prefix: initial state for this chunk ----
    float h = 0.f;
    {
        const int pbase = (b * DI + d) * NC * DS + s;
#pragma unroll
        for (int c = 0; c < NC - 1; c++) {
            if (c < chunk) h = fmaf(g_P[pbase + c * DS], h, g_S[pbase + c * DS]);
        }
    }

    for (int l = 0; l < CHUNK; l += 16) {
        float w[16];
#pragma unroll
        for (int g = 0; g < 4; g++) {
            float4 dv = *(const float4*)(pdt + l + g * 4);
            float4 xv = *(const float4*)(pxc + l + g * 4);
            float4 Bv = *(const float4*)(pB4 + ((l >> 2) + g) * 64);
            float4 Cv = *(const float4*)(pC4 + ((l >> 2) + g) * 64);
            h = fmaf(h, __expf(dv.x * Areg), dv.x * xv.x * Bv.x); w[g * 4 + 0] = h * Cv.x;
            h = fmaf(h, __expf(dv.y * Areg), dv.y * xv.y * Bv.y); w[g * 4 + 1] = h * Cv.y;
            h = fmaf(h, __expf(dv.z * Areg), dv.z * xv.z * Bv.z); w[g * 4 + 2] = h * Cv.z;
            h = fmaf(h, __expf(dv.w * Areg), dv.w * xv.w * Bv.w); w[g * 4 + 3] = h * Cv.w;
        }
        float y  = hreduce16(w, s);
        float xs = pxc[l + s];
        float zs = psz[l + s];
        pyT[l + s] = fmaf(xs, Dd, y) * zs;
    }
}

// ============================================================================
// K4: out-projection GEMM.  out[b,c,l] = sum_d ymT[b,d,l] * W_out[d,c]
// 64(c) x 128(l) tiles, K-tiles of 16 over d, cp.async double-buffered.
// ============================================================================
__global__ __launch_bounds__(256) void k_outproj(const float* __restrict__ Wout,
                                                 float* __restrict__ out) {
    __shared__ float As[2][16][64];
    __shared__ float Bs[2][16][132];
    const int t  = threadIdx.x;
    const int l0 = blockIdx.x * 128, c0 = blockIdx.y * 64, b = blockIdx.z;
    const int ty = t >> 4, tx = t & 15;

    u64 acc[4][4];
#pragma unroll
    for (int i = 0; i < 4; i++)
#pragma unroll
        for (int p = 0; p < 4; p++) acc[i][p] = 0ull;

    const float* ymb = g_ymT + b * DI * LSEQ;
    const int ka = t >> 4, ca = (t & 15) * 4;
    auto pref = [&](int tile, int buf) {
        cp_async16(&As[buf][ka][ca], Wout + (tile * 16 + ka) * DM + c0 + ca);
#pragma unroll
        for (int i = 0; i < 2; i++) {
            int idx = t + i * 256;
            int kb = idx >> 5, lb = (idx & 31) * 4;
            cp_async16(&Bs[buf][kb][lb], ymb + (tile * 16 + kb) * LSEQ + l0 + lb);
        }
    };

    pref(0, 0); cp_commit();

    for (int it = 0; it < 16; it++) {
        const int buf = it & 1;
        cp_wait0();
        __syncthreads();
        if (it + 1 < 16) { pref(it + 1, buf ^ 1); cp_commit(); }
#pragma unroll
        for (int k = 0; k < 16; k++) {
            float4 av = *(const float4*)&As[buf][k][ty * 4];
            u64 aa[4];
            aa[0] = pack2(av.x, av.x); aa[1] = pack2(av.y, av.y);
            aa[2] = pack2(av.z, av.z); aa[3] = pack2(av.w, av.w);
#pragma unroll
            for (int p = 0; p < 4; p++) {
                float2 bp = *(const float2*)&Bs[buf][k][2 * (tx + 16 * p)];
                u64 bb = pack2(bp.x, bp.y);
#pragma unroll
                for (int i = 0; i < 4; i++) acc[i][p] = fma2(aa[i], bb, acc[i][p]);
            }
        }
        __syncthreads();
    }

#pragma unroll
    for (int i = 0; i < 4; i++) {
        int c = c0 + ty * 4 + i;
#pragma unroll
        for (int p = 0; p < 4; p++) {
            float lo, hi; unpack2(acc[i][p], lo, hi);
            int lc = l0 + 2 * (tx + 16 * p);
            float2 v; v.x = lo; v.y = hi;
            *(float2*)&out[(b * DM + c) * LSEQ + lc] = v;
        }
    }
}

// ============================================================================
extern "C" void kernel_launch(void* const* d_in, const int* in_sizes, int n_in,
                              void* d_out, int out_size) {
    (void)in_sizes; (void)n_in; (void)out_size;
    const float* x     = (const float*)d_in[0];
    const float* Win   = (const float*)d_in[1];
    const float* convw = (const float*)d_in[2];
    const float* convb = (const float*)d_in[3];
    const float* Wx    = (const float*)d_in[4];
    const float* Wdt   = (const float*)d_in[5];
    const float* bdt   = (const float*)d_in[6];
    const float* Alog  = (const float*)d_in[7];
    const float* Dvec  = (const float*)d_in[8];
    const float* Wout  = (const float*)d_in[9];
    float* out = (float*)d_out;

    k_inproj   <<<dim3(64, 4, 2), 256>>>(x, Win);
    k_conv_proj<<<256, 256>>>(convw, convb, Wx, Wdt, bdt);
    k_scan1    <<<1024, 128>>>(Alog);
    k_scan3    <<<1024, 128>>>(Alog, Dvec);
    k_outproj  <<<dim3(32, 4, 2), 256>>>(Wout, out);
}

// round 10
// speedup vs baseline: 2.7260x; 1.0412x over previous
#include <cuda_runtime.h>

#define BSZ  2
#define DM   256
#define LSEQ 4096
#define DI   256
#define DS   16
#define NC   32
#define CHUNK (LSEQ / NC)   // 128

// ---------------- scratch (static device globals; no runtime alloc) ----------
__device__ float g_xs [BSZ*LSEQ*DI];   // in-proj left half          [b][l][d]
__device__ float g_szT[BSZ*DI*LSEQ];   // silu(z) TRANSPOSED         [b][d][l]
__device__ float g_xc [BSZ*DI*LSEQ];   // conv+silu output           [b][d][l]
__device__ float g_dt [BSZ*DI*LSEQ];   // softplus(dt)               [b][d][l]
__device__ float g_Bm [BSZ*LSEQ*DS];   // B packed  [b][l/4][s][l%4]
__device__ float g_Cm [BSZ*LSEQ*DS];   // C packed  [b][l/4][s][l%4]
__device__ float g_ymT[BSZ*DI*LSEQ];   // (y + xc*D)*silu(z)         [b][d][l]
__device__ float g_S  [BSZ*DI*NC*DS];  // chunk-final local states
__device__ float g_P  [BSZ*DI*NC*DS];  // chunk decay products

typedef unsigned long long u64;

__device__ __forceinline__ u64 pack2(float lo, float hi) {
    u64 r; asm("mov.b64 %0, {%1, %2};" : "=l"(r) : "f"(lo), "f"(hi)); return r;
}
__device__ __forceinline__ void unpack2(u64 v, float& lo, float& hi) {
    asm("mov.b64 {%0, %1}, %2;" : "=f"(lo), "=f"(hi) : "l"(v));
}
__device__ __forceinline__ u64 fma2(u64 a, u64 b, u64 c) {
    u64 d; asm("fma.rn.f32x2 %0, %1, %2, %3;" : "=l"(d) : "l"(a), "l"(b), "l"(c)); return d;
}
__device__ __forceinline__ float silu_f(float v) { return v / (1.f + __expf(-v)); }

__device__ __forceinline__ void cp_async16(void* smem, const void* g) {
    unsigned sa = (unsigned)__cvta_generic_to_shared(smem);
    asm volatile("cp.async.cg.shared.global [%0], [%1], 16;\n" :: "r"(sa), "l"(g));
}
__device__ __forceinline__ void cp_commit() {
    asm volatile("cp.async.commit_group;\n");
}
__device__ __forceinline__ void cp_wait0() {
    asm volatile("cp.async.wait_group 0;\n");
}

// Exchange-halving butterfly: reduce 16 independent sums (w[j], one per step)
// across the 16 lanes of a half-warp. 15 shuffles total. Result for step j
// lands in lane j (returned in w[0] of lane s=j).
__device__ __forceinline__ float hreduce16(float* w, int s) {
#pragma unroll
    for (int i = 0; i < 8; i++) {
        float snd = (s & 8) ? w[i] : w[i + 8];
        float kp  = (s & 8) ? w[i + 8] : w[i];
        w[i] = kp + __shfl_xor_sync(0xffffffffu, snd, 8, 16);
    }
#pragma unroll
    for (int i = 0; i < 4; i++) {
        float snd = (s & 4) ? w[i] : w[i + 4];
        float kp  = (s & 4) ? w[i + 4] : w[i];
        w[i] = kp + __shfl_xor_sync(0xffffffffu, snd, 4, 16);
    }
#pragma unroll
    for (int i = 0; i < 2; i++) {
        float snd = (s & 2) ? w[i] : w[i + 2];
        float kp  = (s & 2) ? w[i + 2] : w[i];
        w[i] = kp + __shfl_xor_sync(0xffffffffu, snd, 2, 16);
    }
    {
        float snd = (s & 1) ? w[0] : w[1];
        float kp  = (s & 1) ? w[1] : w[0];
        w[0] = kp + __shfl_xor_sync(0xffffffffu, snd, 1, 16);
    }
    return w[0];
}

// ============================================================================
// K1: in-projection GEMM.  out[b,l,j] = sum_c x[b,c,l] * W_in[c,j]
// 64(l) x 128(j) tiles, K-tiles of 16, cp.async double-buffered.
// xs half -> [b][l][d]; z half -> silu -> TRANSPOSED [b][d][l].
// ============================================================================
__global__ __launch_bounds__(256) void k_inproj(const float* __restrict__ x,
                                                const float* __restrict__ Win) {
    __shared__ float As[2][16][64];
    __shared__ float Bs[2][16][132];
    const int t  = threadIdx.x;
    const int l0 = blockIdx.x * 64, j0 = blockIdx.y * 128, b = blockIdx.z;
    const int ty = t >> 4, tx = t & 15;
    const float* xb = x + b * DM * LSEQ;

    u64 acc[4][4];
#pragma unroll
    for (int i = 0; i < 4; i++)
#pragma unroll
        for (int p = 0; p < 4; p++) acc[i][p] = 0ull;

    const int ka = t >> 4, ja = (t & 15) * 4;                 // A: 16x64
    auto pref = [&](int tile, int buf) {
        cp_async16(&As[buf][ka][ja], xb + (tile * 16 + ka) * LSEQ + l0 + ja);
#pragma unroll
        for (int i = 0; i < 2; i++) {
            int idx = t + i * 256;
            int kb = idx >> 5, jb = (idx & 31) * 4;
            cp_async16(&Bs[buf][kb][jb], Win + (tile * 16 + kb) * (2 * DI) + j0 + jb);
        }
    };

    pref(0, 0); cp_commit();

    for (int it = 0; it < 16; it++) {
        const int buf = it & 1;
        cp_wait0();
        __syncthreads();
        if (it + 1 < 16) { pref(it + 1, buf ^ 1); cp_commit(); }
#pragma unroll
        for (int k = 0; k < 16; k++) {
            float4 av = *(const float4*)&As[buf][k][ty * 4];
            u64 aa[4];
            aa[0] = pack2(av.x, av.x); aa[1] = pack2(av.y, av.y);
            aa[2] = pack2(av.z, av.z); aa[3] = pack2(av.w, av.w);
#pragma unroll
            for (int p = 0; p < 4; p++) {
                float2 bp = *(const float2*)&Bs[buf][k][2 * (tx + 16 * p)];
                u64 bb = pack2(bp.x, bp.y);
#pragma unroll
                for (int i = 0; i < 4; i++) acc[i][p] = fma2(aa[i], bb, acc[i][p]);
            }
        }
        __syncthreads();
    }

    if (j0 < DI) {
#pragma unroll
        for (int i = 0; i < 4; i++) {
            int l = l0 + ty * 4 + i;
#pragma unroll
            for (int p = 0; p < 4; p++) {
                float lo, hi; unpack2(acc[i][p], lo, hi);
                int j = j0 + 2 * (tx + 16 * p);
                float2 v; v.x = lo; v.y = hi;
                *(float2*)&g_xs[(b * LSEQ + l) * DI + j] = v;
            }
        }
    } else {
        // z half: silu + transposed store [d][l]
        float lv[4][4], hv[4][4];
#pragma unroll
        for (int i = 0; i < 4; i++)
#pragma unroll
            for (int p = 0; p < 4; p++) unpack2(acc[i][p], lv[i][p], hv[i][p]);
#pragma unroll
        for (int p = 0; p < 4; p++) {
            int jbase = (j0 - DI) + 2 * (tx + 16 * p);
            float4 v0, v1;
            v0.x = silu_f(lv[0][p]); v0.y = silu_f(lv[1][p]);
            v0.z = silu_f(lv[2][p]); v0.w = silu_f(lv[3][p]);
            v1.x = silu_f(hv[0][p]); v1.y = silu_f(hv[1][p]);
            v1.z = silu_f(hv[2][p]); v1.w = silu_f(hv[3][p]);
            *(float4*)&g_szT[(b * DI + jbase)     * LSEQ + l0 + ty * 4] = v0;
            *(float4*)&g_szT[(b * DI + jbase + 1) * LSEQ + l0 + ty * 4] = v1;
        }
    }
}

// ============================================================================
// K2: causal depthwise conv(4) + silu -> xc [d][l]; dbc = xc @ W_x;
//     dt = softplus(dbc[:, :16] @ W_dt + b_dt) -> [d][l];
//     B/C packed [l/4][s][l%4].
// ============================================================================
__global__ __launch_bounds__(256) void k_conv_proj(const float* __restrict__ convw,
                                                   const float* __restrict__ convb,
                                                   const float* __restrict__ Wx,
                                                   const float* __restrict__ Wdt,
                                                   const float* __restrict__ bdt) {
    __shared__ float xc_s[32][257];   // reused as dt staging in phase C
    __shared__ float dbc_s[32][49];
    const int t  = threadIdx.x;
    const int b  = blockIdx.x >> 7;
    const int l0 = (blockIdx.x & 127) * 32;

    // ---- Phase A: conv + silu (thread t owns channel d = t) ----
    {
        const int d = t;
        const float w0 = convw[d * 4 + 0], w1 = convw[d * 4 + 1];
        const float w2 = convw[d * 4 + 2], w3 = convw[d * 4 + 3];
        const float cb = convb[d];
        const float* pxs = g_xs + b * LSEQ * DI + d;
        float x0, x1, x2;
        if (l0 == 0) { x0 = x1 = x2 = 0.f; }
        else { x0 = pxs[(l0 - 3) * DI]; x1 = pxs[(l0 - 2) * DI]; x2 = pxs[(l0 - 1) * DI]; }
        for (int j = 0; j < 32; j++) {
            float x3 = pxs[(l0 + j) * DI];
            float c  = cb + w0 * x0 + w1 * x1 + w2 * x2 + w3 * x3;
            xc_s[j][d] = silu_f(c);
            x0 = x1; x1 = x2; x2 = x3;
        }
    }
    __syncthreads();

    // ---- transposed coalesced write of xc to [d][l] ----
    for (int i = t; i < 32 * DI; i += 256) {
        int d2 = i >> 5, r2 = i & 31;
        g_xc[(b * DI + d2) * LSEQ + l0 + r2] = xc_s[r2][d2];
    }

    // ---- Phase B: dbc[r][0..47] = xc[r] @ W_x ----
    {
        const int r = t & 31, g = t >> 5;   // g in 0..7, 6 cols each
        float acc[6];
#pragma unroll
        for (int jj = 0; jj < 6; jj++) acc[jj] = 0.f;
        const float* wbase = Wx + g * 6;
        for (int c = 0; c < DI; c++) {
            float xv = xc_s[r][c];
            const float2* wp = (const float2*)(wbase + c * 48);
            float2 wa = __ldg(wp), wb = __ldg(wp + 1), wc = __ldg(wp + 2);
            acc[0] = fmaf(xv, wa.x, acc[0]); acc[1] = fmaf(xv, wa.y, acc[1]);
            acc[2] = fmaf(xv, wb.x, acc[2]); acc[3] = fmaf(xv, wb.y, acc[3]);
            acc[4] = fmaf(xv, wc.x, acc[4]); acc[5] = fmaf(xv, wc.y, acc[5]);
        }
#pragma unroll
        for (int jj = 0; jj < 6; jj++) dbc_s[r][g * 6 + jj] = acc[jj];
    }
    __syncthreads();

    // ---- Phase C: dt = softplus(dbc[:, :16] @ W_dt + b_dt) into xc_s ----
    {
        const int d = t;
        float wdt[16];
#pragma unroll
        for (int k = 0; k < 16; k++) wdt[k] = Wdt[k * DI + d];
        const float bd = bdt[d];
        for (int r = 0; r < 32; r++) {
            float a = bd;
#pragma unroll
            for (int k = 0; k < 16; k++) a = fmaf(dbc_s[r][k], wdt[k], a);
            xc_s[r][d] = (a > 20.f) ? a : log1pf(__expf(a));
        }
    }
    __syncthreads();

    // ---- transposed coalesced write of dt to [d][l] ----
    for (int i = t; i < 32 * DI; i += 256) {
        int d2 = i >> 5, r2 = i & 31;
        g_dt[(b * DI + d2) * LSEQ + l0 + r2] = xc_s[r2][d2];
    }

    // ---- packed coalesced write of B / C: [l/4][s][l%4] ----
    {
        const int base = (b * LSEQ + l0) * DS;
        for (int i = t; i < 32 * DS; i += 256) {
            int g4 = i >> 6, s = (i >> 2) & 15, r2 = i & 3;
            int r = g4 * 4 + r2;
            g_Bm[base + i] = dbc_s[r][16 + s];
            g_Cm[base + i] = dbc_s[r][32 + s];
        }
    }
}

// ============================================================================
// K3a: per-chunk local scan -> S (final h with h0=0) and P = exp(A * sum dt).
// half-warp = one (b,d,chunk); lane = state. 16384 half-warps.
// Mapping: d fast, chunk slow -> all 16 half-warps of a block share one chunk
// (B loads hit the same L1 lines).
// ============================================================================
__global__ __launch_bounds__(256) void k_scan1(const float* __restrict__ Alog) {
    const int t = threadIdx.x;
    const int hw = blockIdx.x * 16 + (t >> 4);
    const int d = hw & (DI - 1);
    const int chunk = (hw >> 8) & (NC - 1);
    const int b = hw >> 13;
    const int s = t & 15;
    const float Areg = -__expf(Alog[d * DS + s]);
    const int l0 = chunk * CHUNK;
    const float* pdt = g_dt + (b * DI + d) * LSEQ + l0;
    const float* pxc = g_xc + (b * DI + d) * LSEQ + l0;
    const float* pB4 = g_Bm + (b * LSEQ + l0) * DS + s * 4;

    float h = 0.f, dts = 0.f;
    float4 dv = *(const float4*)pdt;
    float4 xv = *(const float4*)pxc;
    float4 Bv = *(const float4*)pB4;

    for (int l = 0; l < CHUNK; l += 4) {
        float4 dn, xn, Bn;
        if (l + 4 < CHUNK) {
            dn = *(const float4*)(pdt + l + 4);
            xn = *(const float4*)(pxc + l + 4);
            Bn = *(const float4*)(pB4 + (l >> 2) * 64 + 64);
        }
        h = fmaf(h, __expf(dv.x * Areg), dv.x * xv.x * Bv.x);
        h = fmaf(h, __expf(dv.y * Areg), dv.y * xv.y * Bv.y);
        h = fmaf(h, __expf(dv.z * Areg), dv.z * xv.z * Bv.z);
        h = fmaf(h, __expf(dv.w * Areg), dv.w * xv.w * Bv.w);
        dts += (dv.x + dv.y) + (dv.z + dv.w);
        dv = dn; xv = xn; Bv = Bn;
    }
    const int idx = ((b * DI + d) * NC + chunk) * DS + s;
    g_S[idx] = h;
    g_P[idx] = __expf(Areg * dts);
}

// ============================================================================
// K3b: per-chunk scan with true initial state (self-stitched prefix).
// Same d-fast/chunk-slow mapping for intra-block B/C line reuse.
// Reduction batched over 16 steps via exchange-halving butterfly (15 shfl).
// Emits g_ymT = (y + xc*D) * silu(z)   in [b][d][l] layout (coalesced store).
// ============================================================================
__global__ __launch_bounds__(256) void k_scan3(const float* __restrict__ Alog,
                                               const float* __restrict__ Dvec) {
    const int t = threadIdx.x;
    const int hw = blockIdx.x * 16 + (t >> 4);
    const int d = hw & (DI - 1);
    const int chunk = (hw >> 8) & (NC - 1);
    const int b = hw >> 13;
    const int s = t & 15;
    const float Areg = -__expf(Alog[d * DS + s]);
    const float Dd = Dvec[d];
    const int l0 = chunk * CHUNK;
    const float* pdt = g_dt  + (b * DI + d) * LSEQ + l0;
    const float* pxc = g_xc  + (b * DI + d) * LSEQ + l0;
    const float* psz = g_szT + (b * DI + d) * LSEQ + l0;
    const float* pB4 = g_Bm  + (b * LSEQ + l0) * DS + s * 4;
    const float* pC4 = g_Cm  + (b * LSEQ + l0) * DS + s * 4;
    float*       pyT = g_ymT + (b * DI + d) * LSEQ + l0;

    // ---- self-stitched prefix: initial state for this chunk ----
    float h = 0.f;
    {
        const int pbase = (b * DI + d) * NC * DS + s;
#pragma unroll
        for (int c = 0; c < NC - 1; c++) {
            if (c < chunk) h = fmaf(g_P[pbase + c * DS], h, g_S[pbase + c * DS]);
        }
    }

    for (int l = 0; l < CHUNK; l += 16) {
        float w[16];
#pragma unroll
        for (int g = 0; g < 4; g++) {
            float4 dv = *(const float4*)(pdt + l + g * 4);
            float4 xv = *(const float4*)(pxc + l + g * 4);
            float4 Bv = *(const float4*)(pB4 + ((l >> 2) + g) * 64);
            float4 Cv = *(const float4*)(pC4 + ((l >> 2) + g) * 64);
            h = fmaf(h, __expf(dv.x * Areg), dv.x * xv.x * Bv.x); w[g * 4 + 0] = h * Cv.x;
            h = fmaf(h, __expf(dv.y * Areg), dv.y * xv.y * Bv.y); w[g * 4 + 1] = h * Cv.y;
            h = fmaf(h, __expf(dv.z * Areg), dv.z * xv.z * Bv.z); w[g * 4 + 2] = h * Cv.z;
            h = fmaf(h, __expf(dv.w * Areg), dv.w * xv.w * Bv.w); w[g * 4 + 3] = h * Cv.w;
        }
        float y  = hreduce16(w, s);
        float xs = pxc[l + s];
        float zs = psz[l + s];
        pyT[l + s] = fmaf(xs, Dd, y) * zs;
    }
}

// ============================================================================
// K4: out-projection GEMM.  out[b,c,l] = sum_d ymT[b,d,l] * W_out[d,c]
// 64(c) x 128(l) tiles, K-tiles of 16 over d, cp.async double-buffered.
// ============================================================================
__global__ __launch_bounds__(256) void k_outproj(const float* __restrict__ Wout,
                                                 float* __restrict__ out) {
    __shared__ float As[2][16][64];
    __shared__ float Bs[2][16][132];
    const int t  = threadIdx.x;
    const int l0 = blockIdx.x * 128, c0 = blockIdx.y * 64, b = blockIdx.z;
    const int ty = t >> 4, tx = t & 15;

    u64 acc[4][4];
#pragma unroll
    for (int i = 0; i < 4; i++)
#pragma unroll
        for (int p = 0; p < 4; p++) acc[i][p] = 0ull;

    const float* ymb = g_ymT + b * DI * LSEQ;
    const int ka = t >> 4, ca = (t & 15) * 4;
    auto pref = [&](int tile, int buf) {
        cp_async16(&As[buf][ka][ca], Wout + (tile * 16 + ka) * DM + c0 + ca);
#pragma unroll
        for (int i = 0; i < 2; i++) {
            int idx = t + i * 256;
            int kb = idx >> 5, lb = (idx & 31) * 4;
            cp_async16(&Bs[buf][kb][lb], ymb + (tile * 16 + kb) * LSEQ + l0 + lb);
        }
    };

    pref(0, 0); cp_commit();

    for (int it = 0; it < 16; it++) {
        const int buf = it & 1;
        cp_wait0();
        __syncthreads();
        if (it + 1 < 16) { pref(it + 1, buf ^ 1); cp_commit(); }
#pragma unroll
        for (int k = 0; k < 16; k++) {
            float4 av = *(const float4*)&As[buf][k][ty * 4];
            u64 aa[4];
            aa[0] = pack2(av.x, av.x); aa[1] = pack2(av.y, av.y);
            aa[2] = pack2(av.z, av.z); aa[3] = pack2(av.w, av.w);
#pragma unroll
            for (int p = 0; p < 4; p++) {
                float2 bp = *(const float2*)&Bs[buf][k][2 * (tx + 16 * p)];
                u64 bb = pack2(bp.x, bp.y);
#pragma unroll
                for (int i = 0; i < 4; i++) acc[i][p] = fma2(aa[i], bb, acc[i][p]);
            }
        }
        __syncthreads();
    }

#pragma unroll
    for (int i = 0; i < 4; i++) {
        int c = c0 + ty * 4 + i;
#pragma unroll
        for (int p = 0; p < 4; p++) {
            float lo, hi; unpack2(acc[i][p], lo, hi);
            int lc = l0 + 2 * (tx + 16 * p);
            float2 v; v.x = lo; v.y = hi;
            *(float2*)&out[(b * DM + c) * LSEQ + lc] = v;
        }
    }
}

// ============================================================================
extern "C" void kernel_launch(void* const* d_in, const int* in_sizes, int n_in,
                              void* d_out, int out_size) {
    (void)in_sizes; (void)n_in; (void)out_size;
    const float* x     = (const float*)d_in[0];
    const float* Win   = (const float*)d_in[1];
    const float* convw = (const float*)d_in[2];
    const float* convb = (const float*)d_in[3];
    const float* Wx    = (const float*)d_in[4];
    const float* Wdt   = (const float*)d_in[5];
    const float* bdt   = (const float*)d_in[6];
    const float* Alog  = (const float*)d_in[7];
    const float* Dvec  = (const float*)d_in[8];
    const float* Wout  = (const float*)d_in[9];
    float* out = (float*)d_out;

    k_inproj   <<<dim3(64, 4, 2), 256>>>(x, Win);
    k_conv_proj<<<256, 256>>>(convw, convb, Wx, Wdt, bdt);
    k_scan1    <<<1024, 256>>>(Alog);
    k_scan3    <<<1024, 256>>>(Alog, Dvec);
    k_outproj  <<<dim3(32, 4, 2), 256>>>(Wout, out);
}

// round 11
// speedup vs baseline: 2.9913x; 1.0973x over previous
#include <cuda_runtime.h>

#define BSZ  2
#define DM   256
#define LSEQ 4096
#define DI   256
#define DS   16
#define NC   32
#define CHUNK (LSEQ / NC)   // 128
#define ROWP 132            // padded smem row stride (floats), 528B = 33 banks

// ---------------- scratch (static device globals; no runtime alloc) ----------
__device__ float g_xs [BSZ*LSEQ*DI];   // in-proj left half          [b][l][d]
__device__ float g_szT[BSZ*DI*LSEQ];   // silu(z) TRANSPOSED         [b][d][l]
__device__ float g_xc [BSZ*DI*LSEQ];   // conv+silu output           [b][d][l]
__device__ float g_dt [BSZ*DI*LSEQ];   // softplus(dt)               [b][d][l]
__device__ float g_Bm [BSZ*LSEQ*DS];   // B packed  [b][l/4][s][l%4]
__device__ float g_Cm [BSZ*LSEQ*DS];   // C packed  [b][l/4][s][l%4]
__device__ float g_ymT[BSZ*DI*LSEQ];   // (y + xc*D)*silu(z)         [b][d][l]
__device__ float g_S  [BSZ*DI*NC*DS];  // chunk-final local states
__device__ float g_P  [BSZ*DI*NC*DS];  // chunk decay products

typedef unsigned long long u64;

__device__ __forceinline__ u64 pack2(float lo, float hi) {
    u64 r; asm("mov.b64 %0, {%1, %2};" : "=l"(r) : "f"(lo), "f"(hi)); return r;
}
__device__ __forceinline__ void unpack2(u64 v, float& lo, float& hi) {
    asm("mov.b64 {%0, %1}, %2;" : "=f"(lo), "=f"(hi) : "l"(v));
}
__device__ __forceinline__ u64 fma2(u64 a, u64 b, u64 c) {
    u64 d; asm("fma.rn.f32x2 %0, %1, %2, %3;" : "=l"(d) : "l"(a), "l"(b), "l"(c)); return d;
}
__device__ __forceinline__ float silu_f(float v) { return v / (1.f + __expf(-v)); }
__device__ __forceinline__ float ex2f(float v) {
    float r; asm("ex2.approx.ftz.f32 %0, %1;" : "=f"(r) : "f"(v)); return r;
}
#define LOG2E 1.4426950408889634f

__device__ __forceinline__ void cp_async16(void* smem, const void* g) {
    unsigned sa = (unsigned)__cvta_generic_to_shared(smem);
    asm volatile("cp.async.cg.shared.global [%0], [%1], 16;\n" :: "r"(sa), "l"(g));
}
__device__ __forceinline__ void cp_commit() {
    asm volatile("cp.async.commit_group;\n");
}
__device__ __forceinline__ void cp_wait0() {
    asm volatile("cp.async.wait_group 0;\n");
}

// Exchange-halving butterfly: reduce 16 independent sums (w[j], one per step)
// across the 16 lanes of a half-warp. 15 shuffles total. Result for step j
// lands in lane j (returned in w[0] of lane s=j).
__device__ __forceinline__ float hreduce16(float* w, int s) {
#pragma unroll
    for (int i = 0; i < 8; i++) {
        float snd = (s & 8) ? w[i] : w[i + 8];
        float kp  = (s & 8) ? w[i + 8] : w[i];
        w[i] = kp + __shfl_xor_sync(0xffffffffu, snd, 8, 16);
    }
#pragma unroll
    for (int i = 0; i < 4; i++) {
        float snd = (s & 4) ? w[i] : w[i + 4];
        float kp  = (s & 4) ? w[i + 4] : w[i];
        w[i] = kp + __shfl_xor_sync(0xffffffffu, snd, 4, 16);
    }
#pragma unroll
    for (int i = 0; i < 2; i++) {
        float snd = (s & 2) ? w[i] : w[i + 2];
        float kp  = (s & 2) ? w[i + 2] : w[i];
        w[i] = kp + __shfl_xor_sync(0xffffffffu, snd, 2, 16);
    }
    {
        float snd = (s & 1) ? w[0] : w[1];
        float kp  = (s & 1) ? w[1] : w[0];
        w[0] = kp + __shfl_xor_sync(0xffffffffu, snd, 1, 16);
    }
    return w[0];
}

// ============================================================================
// K1: in-projection GEMM.  out[b,l,j] = sum_c x[b,c,l] * W_in[c,j]
// 64(l) x 128(j) tiles, K-tiles of 16, cp.async double-buffered.
// xs half -> [b][l][d]; z half -> silu -> TRANSPOSED [b][d][l].
// ============================================================================
__global__ __launch_bounds__(256) void k_inproj(const float* __restrict__ x,
                                                const float* __restrict__ Win) {
    __shared__ float As[2][16][64];
    __shared__ float Bs[2][16][132];
    const int t  = threadIdx.x;
    const int l0 = blockIdx.x * 64, j0 = blockIdx.y * 128, b = blockIdx.z;
    const int ty = t >> 4, tx = t & 15;
    const float* xb = x + b * DM * LSEQ;

    u64 acc[4][4];
#pragma unroll
    for (int i = 0; i < 4; i++)
#pragma unroll
        for (int p = 0; p < 4; p++) acc[i][p] = 0ull;

    const int ka = t >> 4, ja = (t & 15) * 4;                 // A: 16x64
    auto pref = [&](int tile, int buf) {
        cp_async16(&As[buf][ka][ja], xb + (tile * 16 + ka) * LSEQ + l0 + ja);
#pragma unroll
        for (int i = 0; i < 2; i++) {
            int idx = t + i * 256;
            int kb = idx >> 5, jb = (idx & 31) * 4;
            cp_async16(&Bs[buf][kb][jb], Win + (tile * 16 + kb) * (2 * DI) + j0 + jb);
        }
    };

    pref(0, 0); cp_commit();

    for (int it = 0; it < 16; it++) {
        const int buf = it & 1;
        cp_wait0();
        __syncthreads();
        if (it + 1 < 16) { pref(it + 1, buf ^ 1); cp_commit(); }
#pragma unroll
        for (int k = 0; k < 16; k++) {
            float4 av = *(const float4*)&As[buf][k][ty * 4];
            u64 aa[4];
            aa[0] = pack2(av.x, av.x); aa[1] = pack2(av.y, av.y);
            aa[2] = pack2(av.z, av.z); aa[3] = pack2(av.w, av.w);
#pragma unroll
            for (int p = 0; p < 4; p++) {
                float2 bp = *(const float2*)&Bs[buf][k][2 * (tx + 16 * p)];
                u64 bb = pack2(bp.x, bp.y);
#pragma unroll
                for (int i = 0; i < 4; i++) acc[i][p] = fma2(aa[i], bb, acc[i][p]);
            }
        }
        __syncthreads();
    }

    if (j0 < DI) {
#pragma unroll
        for (int i = 0; i < 4; i++) {
            int l = l0 + ty * 4 + i;
#pragma unroll
            for (int p = 0; p < 4; p++) {
                float lo, hi; unpack2(acc[i][p], lo, hi);
                int j = j0 + 2 * (tx + 16 * p);
                float2 v; v.x = lo; v.y = hi;
                *(float2*)&g_xs[(b * LSEQ + l) * DI + j] = v;
            }
        }
    } else {
        // z half: silu + transposed store [d][l]
        float lv[4][4], hv[4][4];
#pragma unroll
        for (int i = 0; i < 4; i++)
#pragma unroll
            for (int p = 0; p < 4; p++) unpack2(acc[i][p], lv[i][p], hv[i][p]);
#pragma unroll
        for (int p = 0; p < 4; p++) {
            int jbase = (j0 - DI) + 2 * (tx + 16 * p);
            float4 v0, v1;
            v0.x = silu_f(lv[0][p]); v0.y = silu_f(lv[1][p]);
            v0.z = silu_f(lv[2][p]); v0.w = silu_f(lv[3][p]);
            v1.x = silu_f(hv[0][p]); v1.y = silu_f(hv[1][p]);
            v1.z = silu_f(hv[2][p]); v1.w = silu_f(hv[3][p]);
            *(float4*)&g_szT[(b * DI + jbase)     * LSEQ + l0 + ty * 4] = v0;
            *(float4*)&g_szT[(b * DI + jbase + 1) * LSEQ + l0 + ty * 4] = v1;
        }
    }
}

// ============================================================================
// K2: causal depthwise conv(4) + silu -> xc [d][l]; dbc = xc @ W_x;
//     dt = softplus(dbc[:, :16] @ W_dt + b_dt) -> [d][l];
//     B/C packed [l/4][s][l%4].
// ============================================================================
__global__ __launch_bounds__(256) void k_conv_proj(const float* __restrict__ convw,
                                                   const float* __restrict__ convb,
                                                   const float* __restrict__ Wx,
                                                   const float* __restrict__ Wdt,
                                                   const float* __restrict__ bdt) {
    __shared__ float xc_s[32][257];   // reused as dt staging in phase C
    __shared__ float dbc_s[32][49];
    const int t  = threadIdx.x;
    const int b  = blockIdx.x >> 7;
    const int l0 = (blockIdx.x & 127) * 32;

    // ---- Phase A: conv + silu (thread t owns channel d = t) ----
    {
        const int d = t;
        const float w0 = convw[d * 4 + 0], w1 = convw[d * 4 + 1];
        const float w2 = convw[d * 4 + 2], w3 = convw[d * 4 + 3];
        const float cb = convb[d];
        const float* pxs = g_xs + b * LSEQ * DI + d;
        float x0, x1, x2;
        if (l0 == 0) { x0 = x1 = x2 = 0.f; }
        else { x0 = pxs[(l0 - 3) * DI]; x1 = pxs[(l0 - 2) * DI]; x2 = pxs[(l0 - 1) * DI]; }
        for (int j = 0; j < 32; j++) {
            float x3 = pxs[(l0 + j) * DI];
            float c  = cb + w0 * x0 + w1 * x1 + w2 * x2 + w3 * x3;
            xc_s[j][d] = silu_f(c);
            x0 = x1; x1 = x2; x2 = x3;
        }
    }
    __syncthreads();

    // ---- transposed coalesced write of xc to [d][l] ----
    for (int i = t; i < 32 * DI; i += 256) {
        int d2 = i >> 5, r2 = i & 31;
        g_xc[(b * DI + d2) * LSEQ + l0 + r2] = xc_s[r2][d2];
    }

    // ---- Phase B: dbc[r][0..47] = xc[r] @ W_x ----
    {
        const int r = t & 31, g = t >> 5;   // g in 0..7, 6 cols each
        float acc[6];
#pragma unroll
        for (int jj = 0; jj < 6; jj++) acc[jj] = 0.f;
        const float* wbase = Wx + g * 6;
        for (int c = 0; c < DI; c++) {
            float xv = xc_s[r][c];
            const float2* wp = (const float2*)(wbase + c * 48);
            float2 wa = __ldg(wp), wb = __ldg(wp + 1), wc = __ldg(wp + 2);
            acc[0] = fmaf(xv, wa.x, acc[0]); acc[1] = fmaf(xv, wa.y, acc[1]);
            acc[2] = fmaf(xv, wb.x, acc[2]); acc[3] = fmaf(xv, wb.y, acc[3]);
            acc[4] = fmaf(xv, wc.x, acc[4]); acc[5] = fmaf(xv, wc.y, acc[5]);
        }
#pragma unroll
        for (int jj = 0; jj < 6; jj++) dbc_s[r][g * 6 + jj] = acc[jj];
    }
    __syncthreads();

    // ---- Phase C: dt = softplus(dbc[:, :16] @ W_dt + b_dt) into xc_s ----
    {
        const int d = t;
        float wdt[16];
#pragma unroll
        for (int k = 0; k < 16; k++) wdt[k] = Wdt[k * DI + d];
        const float bd = bdt[d];
        for (int r = 0; r < 32; r++) {
            float a = bd;
#pragma unroll
            for (int k = 0; k < 16; k++) a = fmaf(dbc_s[r][k], wdt[k], a);
            xc_s[r][d] = (a > 20.f) ? a : log1pf(__expf(a));
        }
    }
    __syncthreads();

    // ---- transposed coalesced write of dt to [d][l] ----
    for (int i = t; i < 32 * DI; i += 256) {
        int d2 = i >> 5, r2 = i & 31;
        g_dt[(b * DI + d2) * LSEQ + l0 + r2] = xc_s[r2][d2];
    }

    // ---- packed coalesced write of B / C: [l/4][s][l%4] ----
    {
        const int base = (b * LSEQ + l0) * DS;
        for (int i = t; i < 32 * DS; i += 256) {
            int g4 = i >> 6, s = (i >> 2) & 15, r2 = i & 3;
            int r = g4 * 4 + r2;
            g_Bm[base + i] = dbc_s[r][16 + s];
            g_Cm[base + i] = dbc_s[r][32 + s];
        }
    }
}

// ============================================================================
// K3a: per-chunk local scan -> S (final h with h0=0) and P = exp2(A2 * sum dt).
// Block = 16 d's x one chunk; working set staged in smem via one cp.async burst.
// half-warp = one d; lane = state.
// ============================================================================
__global__ __launch_bounds__(256) void k_scan1(const float* __restrict__ Alog) {
    __shared__ __align__(16) float s_dt[16 * ROWP];
    __shared__ __align__(16) float s_xc[16 * ROWP];
    __shared__ __align__(16) float s_B [CHUNK * DS];

    const int t  = threadIdx.x;
    const int dg    = blockIdx.x & 15;
    const int chunk = (blockIdx.x >> 4) & (NC - 1);
    const int b     = blockIdx.x >> 9;
    const int d0 = dg * 16;
    const int l0 = chunk * CHUNK;

    const float* pdt_g = g_dt + (b * DI + d0) * LSEQ + l0;
    const float* pxc_g = g_xc + (b * DI + d0) * LSEQ + l0;
    const float* pB_g  = g_Bm + (b * LSEQ + l0) * DS;

    // ---- one-shot cp.async fill (24 KB) ----
#pragma unroll
    for (int i = t; i < 512 * 3; i += 256) {
        int r = i >> 9, j = i & 511;
        int w = j >> 5, j16 = (j & 31) * 4;
        if (r == 0)      cp_async16(&s_dt[w * ROWP + j16], pdt_g + w * LSEQ + j16);
        else if (r == 1) cp_async16(&s_xc[w * ROWP + j16], pxc_g + w * LSEQ + j16);
        else             cp_async16(&s_B[j * 4], pB_g + j * 4);
    }
    cp_commit(); cp_wait0();
    __syncthreads();

    const int w = t >> 4, s = t & 15;
    const int d = d0 + w;
    const float A2 = -__expf(Alog[d * DS + s]) * LOG2E;
    const float* sdt = s_dt + w * ROWP;
    const float* sxc = s_xc + w * ROWP;
    const float* sB  = s_B + s * 4;

    float h = 0.f, dts = 0.f;
#pragma unroll 8
    for (int l = 0; l < CHUNK; l += 4) {
        float4 dv = *(const float4*)(sdt + l);
        float4 xv = *(const float4*)(sxc + l);
        float4 Bv = *(const float4*)(sB + (l >> 2) * 64);
        h = fmaf(h, ex2f(dv.x * A2), dv.x * xv.x * Bv.x);
        h = fmaf(h, ex2f(dv.y * A2), dv.y * xv.y * Bv.y);
        h = fmaf(h, ex2f(dv.z * A2), dv.z * xv.z * Bv.z);
        h = fmaf(h, ex2f(dv.w * A2), dv.w * xv.w * Bv.w);
        dts += (dv.x + dv.y) + (dv.z + dv.w);
    }
    const int idx = ((b * DI + d) * NC + chunk) * DS + s;
    g_S[idx] = h;
    g_P[idx] = ex2f(A2 * dts);
}

// ============================================================================
// K3b: per-chunk scan with true initial state (self-stitched prefix).
// Block = 16 d's x one chunk; 40 KB smem staging. Butterfly reduction.
// Emits g_ymT = (y + xc*D) * silu(z)   in [b][d][l] layout (coalesced store).
// ============================================================================
__global__ __launch_bounds__(256) void k_scan3(const float* __restrict__ Alog,
                                               const float* __restrict__ Dvec) {
    __shared__ __align__(16) float s_dt[16 * ROWP];
    __shared__ __align__(16) float s_xc[16 * ROWP];
    __shared__ __align__(16) float s_sz[16 * ROWP];
    __shared__ __align__(16) float s_B [CHUNK * DS];
    __shared__ __align__(16) float s_C [CHUNK * DS];

    const int t  = threadIdx.x;
    const int dg    = blockIdx.x & 15;
    const int chunk = (blockIdx.x >> 4) & (NC - 1);
    const int b     = blockIdx.x >> 9;
    const int d0 = dg * 16;
    const int l0 = chunk * CHUNK;

    const float* pdt_g = g_dt  + (b * DI + d0) * LSEQ + l0;
    const float* pxc_g = g_xc  + (b * DI + d0) * LSEQ + l0;
    const float* psz_g = g_szT + (b * DI + d0) * LSEQ + l0;
    const float* pB_g  = g_Bm  + (b * LSEQ + l0) * DS;
    const float* pC_g  = g_Cm  + (b * LSEQ + l0) * DS;

    // ---- one-shot cp.async fill (40 KB) ----
#pragma unroll
    for (int i = t; i < 512 * 5; i += 256) {
        int r = i >> 9, j = i & 511;
        int w = j >> 5, j16 = (j & 31) * 4;
        if (r == 0)      cp_async16(&s_dt[w * ROWP + j16], pdt_g + w * LSEQ + j16);
        else if (r == 1) cp_async16(&s_xc[w * ROWP + j16], pxc_g + w * LSEQ + j16);
        else if (r == 2) cp_async16(&s_sz[w * ROWP + j16], psz_g + w * LSEQ + j16);
        else if (r == 3) cp_async16(&s_B[j * 4], pB_g + j * 4);
        else             cp_async16(&s_C[j * 4], pC_g + j * 4);
    }
    cp_commit();

    const int w = t >> 4, s = t & 15;
    const int d = d0 + w;
    const float A2 = -__expf(Alog[d * DS + s]) * LOG2E;
    const float Dd = Dvec[d];
    float*       pyT = g_ymT + (b * DI + d) * LSEQ + l0;

    // ---- self-stitched prefix (overlaps with the cp.async fill) ----
    float h = 0.f;
    {
        const int pbase = (b * DI + d) * NC * DS + s;
#pragma unroll
        for (int c = 0; c < NC - 1; c++) {
            if (c < chunk) h = fmaf(g_P[pbase + c * DS], h, g_S[pbase + c * DS]);
        }
    }

    cp_wait0();
    __syncthreads();

    const float* sdt = s_dt + w * ROWP;
    const float* sxc = s_xc + w * ROWP;
    const float* ssz = s_sz + w * ROWP;
    const float* sB  = s_B + s * 4;
    const float* sC  = s_C + s * 4;

    for (int l = 0; l < CHUNK; l += 16) {
        float wv[16];
#pragma unroll
        for (int g = 0; g < 4; g++) {
            float4 dv = *(const float4*)(sdt + l + g * 4);
            float4 xv = *(const float4*)(sxc + l + g * 4);
            float4 Bv = *(const float4*)(sB + ((l >> 2) + g) * 64);
            float4 Cv = *(const float4*)(sC + ((l >> 2) + g) * 64);
            h = fmaf(h, ex2f(dv.x * A2), dv.x * xv.x * Bv.x); wv[g * 4 + 0] = h * Cv.x;
            h = fmaf(h, ex2f(dv.y * A2), dv.y * xv.y * Bv.y); wv[g * 4 + 1] = h * Cv.y;
            h = fmaf(h, ex2f(dv.z * A2), dv.z * xv.z * Bv.z); wv[g * 4 + 2] = h * Cv.z;
            h = fmaf(h, ex2f(dv.w * A2), dv.w * xv.w * Bv.w); wv[g * 4 + 3] = h * Cv.w;
        }
        float y  = hreduce16(wv, s);
        float xs = sxc[l + s];
        float zs = ssz[l + s];
        pyT[l + s] = fmaf(xs, Dd, y) * zs;
    }
}

// ============================================================================
// K4: out-projection GEMM.  out[b,c,l] = sum_d ymT[b,d,l] * W_out[d,c]
// 64(c) x 128(l) tiles, K-tiles of 16 over d, cp.async double-buffered.
// ============================================================================
__global__ __launch_bounds__(256) void k_outproj(const float* __restrict__ Wout,
                                                 float* __restrict__ out) {
    __shared__ float As[2][16][64];
    __shared__ float Bs[2][16][132];
    const int t  = threadIdx.x;
    const int l0 = blockIdx.x * 128, c0 = blockIdx.y * 64, b = blockIdx.z;
    const int ty = t >> 4, tx = t & 15;

    u64 acc[4][4];
#pragma unroll
    for (int i = 0; i < 4; i++)
#pragma unroll
        for (int p = 0; p < 4; p++) acc[i][p] = 0ull;

    const float* ymb = g_ymT + b * DI * LSEQ;
    const int ka = t >> 4, ca = (t & 15) * 4;
    auto pref = [&](int tile, int buf) {
        cp_async16(&As[buf][ka][ca], Wout + (tile * 16 + ka) * DM + c0 + ca);
#pragma unroll
        for (int i = 0; i < 2; i++) {
            int idx = t + i * 256;
            int kb = idx >> 5, lb = (idx & 31) * 4;
            cp_async16(&Bs[buf][kb][lb], ymb + (tile * 16 + kb) * LSEQ + l0 + lb);
        }
    };

    pref(0, 0); cp_commit();

    for (int it = 0; it < 16; it++) {
        const int buf = it & 1;
        cp_wait0();
        __syncthreads();
        if (it + 1 < 16) { pref(it + 1, buf ^ 1); cp_commit(); }
#pragma unroll
        for (int k = 0; k < 16; k++) {
            float4 av = *(const float4*)&As[buf][k][ty * 4];
            u64 aa[4];
            aa[0] = pack2(av.x, av.x); aa[1] = pack2(av.y, av.y);
            aa[2] = pack2(av.z, av.z); aa[3] = pack2(av.w, av.w);
#pragma unroll
            for (int p = 0; p < 4; p++) {
                float2 bp = *(const float2*)&Bs[buf][k][2 * (tx + 16 * p)];
                u64 bb = pack2(bp.x, bp.y);
#pragma unroll
                for (int i = 0; i < 4; i++) acc[i][p] = fma2(aa[i], bb, acc[i][p]);
            }
        }
        __syncthreads();
    }

#pragma unroll
    for (int i = 0; i < 4; i++) {
        int c = c0 + ty * 4 + i;
#pragma unroll
        for (int p = 0; p < 4; p++) {
            float lo, hi; unpack2(acc[i][p], lo, hi);
            int lc = l0 + 2 * (tx + 16 * p);
            float2 v; v.x = lo; v.y = hi;
            *(float2*)&out[(b * DM + c) * LSEQ + lc] = v;
        }
    }
}

// ============================================================================
extern "C" void kernel_launch(void* const* d_in, const int* in_sizes, int n_in,
                              void* d_out, int out_size) {
    (void)in_sizes; (void)n_in; (void)out_size;
    const float* x     = (const float*)d_in[0];
    const float* Win   = (const float*)d_in[1];
    const float* convw = (const float*)d_in[2];
    const float* convb = (const float*)d_in[3];
    const float* Wx    = (const float*)d_in[4];
    const float* Wdt   = (const float*)d_in[5];
    const float* bdt   = (const float*)d_in[6];
    const float* Alog  = (const float*)d_in[7];
    const float* Dvec  = (const float*)d_in[8];
    const float* Wout  = (const float*)d_in[9];
    float* out = (float*)d_out;

    k_inproj   <<<dim3(64, 4, 2), 256>>>(x, Win);
    k_conv_proj<<<256, 256>>>(convw, convb, Wx, Wdt, bdt);
    k_scan1    <<<1024, 256>>>(Alog);
    k_scan3    <<<1024, 256>>>(Alog, Dvec);
    k_outproj  <<<dim3(32, 4, 2), 256>>>(Wout, out);
}